// round 14
// baseline (speedup 1.0000x reference)
#include <cuda_runtime.h>
#include <cuda_bf16.h>
#include <math.h>
#include <stdint.h>

#define NSRC 10000
#define NEDGE 320000
#define DIM 128
#define EDIM 236
#define TOPN 6
#define BN_EPS 1e-5f

// ---------------- scratch (device globals; no allocation allowed) ----------
__device__ float  g_agg[(size_t)NSRC * EDIM];
__device__ float  g_xg[(size_t)NEDGE * DIM];         // holds y = xg + srcterm[sid]
__device__ float  g_srcterm[(size_t)NSRC * DIM];
__device__ float  g_T[(size_t)3 * NSRC * DIM];
__device__ float  g_h2[(size_t)NSRC * DIM];
__device__ float  g_Wc[3 * DIM * DIM];
__device__ float  g_Wei1[3 * EDIM * DIM];
__device__ float  g_cvec[3 * DIM];
__device__ float  g_scores[NEDGE];
__device__ int    g_cnt[NSRC];
__device__ int    g_off[NSRC + 1];
__device__ int    g_cur[NSRC];
__device__ int    g_order[NEDGE];
__device__ double g_tsum[3 * DIM], g_tsumsq[3 * DIM];
__device__ double g_psumB[32 * DIM], g_psumsqB[32 * DIM];
__device__ float  g_ta[3 * DIM], g_tc[3 * DIM];
__device__ float  g_peA[DIM], g_peC[DIM];
__device__ float  g_combB[DIM];
__device__ float  g_cs[128 * TOPN];
__device__ int    g_ci[128 * TOPN];
// pre-split bf16 weights, n-major [n][Kpad]
__device__ __nv_bfloat16 g_Bh[128 * 256],  g_Bl[128 * 256];
__device__ __nv_bfloat16 g_Wbh[3 * 128 * 384], g_Wbl[3 * 128 * 384];
__device__ __nv_bfloat16 g_Wch[128 * 384], g_Wcl[128 * 384];
__device__ __nv_bfloat16 g_l2h[128 * 128], g_l2l[128 * 128];
__device__ __nv_bfloat16 g_psh[128 * 128], g_psl[128 * 128];

// ---------------- small utility kernels ------------------------------------
__global__ void k_reset() {
    int t = blockIdx.x * blockDim.x + threadIdx.x;
    if (t < NSRC) g_cnt[t] = 0;
    if (t < 3 * DIM) { g_tsum[t] = 0.0; g_tsumsq[t] = 0.0; }
    if (t < 32 * DIM) { g_psumB[t] = 0.0; g_psumsqB[t] = 0.0; }
}

__global__ void k_hist(const int* __restrict__ sid) {
    int e = blockIdx.x * blockDim.x + threadIdx.x;
    if (e < NEDGE) atomicAdd(&g_cnt[sid[e]], 1);
}

__global__ void k_scan() {
    __shared__ int s[1024];
    int t = threadIdx.x;
    int base = t * 10;
    int loc[10];
    int acc = 0;
#pragma unroll
    for (int j = 0; j < 10; j++) {
        int idx = base + j;
        int v = (idx < NSRC) ? g_cnt[idx] : 0;
        loc[j] = acc; acc += v;
    }
    s[t] = acc;
    __syncthreads();
    for (int off = 1; off < 1024; off <<= 1) {
        int v = (t >= off) ? s[t - off] : 0;
        __syncthreads();
        s[t] += v;
        __syncthreads();
    }
    int pre = (t > 0) ? s[t - 1] : 0;
#pragma unroll
    for (int j = 0; j < 10; j++) {
        int idx = base + j;
        if (idx < NSRC) { g_off[idx] = pre + loc[j]; g_cur[idx] = pre + loc[j]; }
    }
    if (t == 0) g_off[NSRC] = NEDGE;
}

__global__ void k_scatter(const int* __restrict__ sid) {
    int e = blockIdx.x * blockDim.x + threadIdx.x;
    if (e < NEDGE) {
        int p = atomicAdd(&g_cur[sid[e]], 1);
        g_order[p] = e;
    }
}

__device__ __forceinline__ void splitbf(float v, __nv_bfloat16& h, __nv_bfloat16& l) {
    h = __float2bfloat16(v);
    l = __float2bfloat16(v - __bfloat162float(h));
}

__global__ void k_prepB(const float* __restrict__ ptW) {
    int idx = blockIdx.x * 256 + threadIdx.x;
    if (idx >= 128 * 256) return;
    int k = idx >> 7, n = idx & 127;
    float b = (k < EDIM) ? ptW[(size_t)k * DIM + n] : 0.f;
    __nv_bfloat16 h, l; splitbf(b, h, l);
    g_Bh[n * 256 + k] = h;
    g_Bl[n * 256 + k] = l;
}

__global__ void k_prepWbig(const float* __restrict__ w1) {
    int i = blockIdx.y;
    int idx = blockIdx.x * 256 + threadIdx.x;
    int n = idx / 384, k = idx % 384;
    float v = 0.f;
    if (k < EDIM) v = g_Wei1[i * EDIM * DIM + k * DIM + n];
    else if (k < EDIM + DIM) v = w1[i * DIM * DIM + (k - EDIM) * DIM + n];
    __nv_bfloat16 h, l; splitbf(v, h, l);
    g_Wbh[i * 128 * 384 + n * 384 + k] = h;
    g_Wbl[i * 128 * 384 + n * 384 + k] = l;
}

__global__ void k_prepWgen(const float* __restrict__ src, __nv_bfloat16* __restrict__ dh,
                           __nv_bfloat16* __restrict__ dl, int K, int Kpad) {
    int idx = blockIdx.x * 256 + threadIdx.x;
    if (idx >= 128 * Kpad) return;
    int n = idx / Kpad, k = idx % Kpad;
    float v = (k < K) ? src[(size_t)k * DIM + n] : 0.f;
    __nv_bfloat16 h, l; splitbf(v, h, l);
    dh[n * Kpad + k] = h;
    dl[n * Kpad + k] = l;
}

__global__ void k_cvec(const float* __restrict__ ceb, const float* __restrict__ w1) {
    int i = blockIdx.x, n = threadIdx.x;
    float s = 0.f;
    for (int k = 0; k < DIM; k++)
        s += ceb[i * DIM + k] * w1[i * DIM * DIM + k * DIM + n];
    g_cvec[i * DIM + n] = s;
}

__global__ void k_agg(const float* __restrict__ pf) {
    int w = (blockIdx.x * blockDim.x + threadIdx.x) >> 5;
    int lane = threadIdx.x & 31;
    if (w >= NSRC) return;
    float4 a0 = make_float4(0.f, 0.f, 0.f, 0.f);
    float4 a1 = make_float4(0.f, 0.f, 0.f, 0.f);
    int s = g_off[w], e2 = g_off[w + 1];
    for (int p = s; p < e2; p++) {
        const float4* r = (const float4*)(pf + (size_t)g_order[p] * EDIM);
        float4 v = __ldg(r + lane);
        a0.x += fmaxf(v.x, 0.f); a0.y += fmaxf(v.y, 0.f);
        a0.z += fmaxf(v.z, 0.f); a0.w += fmaxf(v.w, 0.f);
        if (lane < 27) {
            float4 v2 = __ldg(r + 32 + lane);
            a1.x += fmaxf(v2.x, 0.f); a1.y += fmaxf(v2.y, 0.f);
            a1.z += fmaxf(v2.z, 0.f); a1.w += fmaxf(v2.w, 0.f);
        }
    }
    float4* outp = (float4*)(g_agg + (size_t)w * EDIM);
    outp[lane] = a0;
    if (lane < 27) outp[32 + lane] = a1;
}

// ---------------- small fp32 GEMM (C = A@W), batched over blockIdx.y --------
__global__ void __launch_bounds__(256)
gemm128(const float* __restrict__ A, int M, int K, int lda, long astr,
        const float* __restrict__ W, long wstr,
        float* __restrict__ C, long cstr) {
    int bz = blockIdx.y;
    A += (size_t)bz * astr;
    W += (size_t)bz * wstr;
    C += (size_t)bz * cstr;

    __shared__ float sA[8][128];
    __shared__ float sW[8][128];
    int tid = threadIdx.x;
    int row0 = blockIdx.x * 128;
    int tx = tid & 15, ty = tid >> 4;
    float acc[8][8];
#pragma unroll
    for (int i = 0; i < 8; i++)
#pragma unroll
        for (int j = 0; j < 8; j++) acc[i][j] = 0.f;

    int ar = tid >> 1;
    int ac = (tid & 1) * 4;
    int wk = (tid * 4) >> 7;
    int wc = (tid * 4) & 127;

    for (int kk = 0; kk < K; kk += 8) {
        float4 av = make_float4(0.f, 0.f, 0.f, 0.f);
        int grow = row0 + ar;
        if (grow < M) {
            int k = kk + ac;
            if (k + 3 < K) {
                av = *(const float4*)(A + (size_t)grow * lda + k);
            } else {
#pragma unroll
                for (int j = 0; j < 4; j++) {
                    int kj = k + j;
                    ((float*)&av)[j] = (kj < K) ? A[(size_t)grow * lda + kj] : 0.f;
                }
            }
        }
        sA[ac + 0][ar] = av.x; sA[ac + 1][ar] = av.y;
        sA[ac + 2][ar] = av.z; sA[ac + 3][ar] = av.w;

        float4 wv = make_float4(0.f, 0.f, 0.f, 0.f);
        if (kk + wk < K) wv = *(const float4*)(W + (size_t)(kk + wk) * 128 + wc);
        *(float4*)&sW[wk][wc] = wv;
        __syncthreads();

#pragma unroll
        for (int k = 0; k < 8; k++) {
            float4 a0 = *(float4*)&sA[k][ty * 8];
            float4 a1 = *(float4*)&sA[k][ty * 8 + 4];
            float4 b0 = *(float4*)&sW[k][tx * 8];
            float4 b1 = *(float4*)&sW[k][tx * 8 + 4];
            float ra[8] = {a0.x, a0.y, a0.z, a0.w, a1.x, a1.y, a1.z, a1.w};
            float rb[8] = {b0.x, b0.y, b0.z, b0.w, b1.x, b1.y, b1.z, b1.w};
#pragma unroll
            for (int i = 0; i < 8; i++)
#pragma unroll
                for (int j = 0; j < 8; j++) acc[i][j] += ra[i] * rb[j];
        }
        __syncthreads();
    }
#pragma unroll
    for (int i = 0; i < 8; i++) {
        int row = row0 + ty * 8 + i;
        if (row < M)
#pragma unroll
            for (int j = 0; j < 8; j++)
                C[(size_t)row * DIM + tx * 8 + j] = acc[i][j];
    }
}

// =================== shared HMMA split-bf16 machinery =======================
#define LDE 72
#define LDW 36
#define ROWB 144                       // bytes per smem row
#define TILEB (128 * ROWB)             // 18432 bytes
#define EG_SMEM (4 * TILEB)            // Ah, Al, Bh, Bl = 73728 bytes

__device__ __forceinline__ void mma16816(float* c, const uint32_t* a, const uint32_t* b) {
    asm volatile(
        "mma.sync.aligned.m16n8k16.row.col.f32.bf16.bf16.f32 "
        "{%0,%1,%2,%3}, {%4,%5,%6,%7}, {%8,%9}, {%0,%1,%2,%3};"
        : "+f"(c[0]), "+f"(c[1]), "+f"(c[2]), "+f"(c[3])
        : "r"(a[0]), "r"(a[1]), "r"(a[2]), "r"(a[3]), "r"(b[0]), "r"(b[1]));
}
__device__ __forceinline__ void ldsm4(uint32_t* r, uint32_t a) {
    asm volatile("ldmatrix.sync.aligned.m8n8.x4.shared.b16 {%0,%1,%2,%3}, [%4];"
                 : "=r"(r[0]), "=r"(r[1]), "=r"(r[2]), "=r"(r[3]) : "r"(a));
}
__device__ __forceinline__ uint32_t packbf(float x, float y) {
    union { __nv_bfloat162 b; uint32_t u; } c;
    c.b = __float22bfloat162_rn(make_float2(x, y));
    return c.u;
}

// lane-specific ldmatrix base offsets (bytes) within a tile buffer
__device__ __forceinline__ uint32_t a_ldsm_off(int lane, int warpM) {
    int row = warpM * 64 + (lane & 7) + ((lane >> 3) & 1) * 8;
    return (uint32_t)row * ROWB + (uint32_t)((lane >> 4) & 1) * 16;
}
__device__ __forceinline__ uint32_t b_ldsm_off(int lane, int warpN) {
    int row = warpN * 32 + ((lane >> 4) & 1) * 8 + (lane & 7);
    return (uint32_t)row * ROWB + (uint32_t)((lane >> 3) & 1) * 16;
}

__device__ __forceinline__ void mma_chunk(uint32_t aH, uint32_t aL,
                                          uint32_t bH, uint32_t bL,
                                          float acc[4][4][4], int ksmax) {
    for (int ks = 0; ks < ksmax; ks++) {
        uint32_t kb = (uint32_t)ks * 32;
        uint32_t bh[8], bl[8];
        ldsm4(&bh[0], bH + kb);
        ldsm4(&bh[4], bH + 16 * ROWB + kb);
        ldsm4(&bl[0], bL + kb);
        ldsm4(&bl[4], bL + 16 * ROWB + kb);
#pragma unroll
        for (int mt = 0; mt < 4; mt++) {
            uint32_t ah[4], al[4];
            ldsm4(ah, aH + (uint32_t)mt * 16 * ROWB + kb);
            ldsm4(al, aL + (uint32_t)mt * 16 * ROWB + kb);
#pragma unroll
            for (int nt = 0; nt < 4; nt++) {
                mma16816(acc[mt][nt], ah, &bh[nt * 2]);
                mma16816(acc[mt][nt], ah, &bl[nt * 2]);
                mma16816(acc[mt][nt], al, &bh[nt * 2]);
            }
        }
    }
}

__device__ __forceinline__ void store_split(uint32_t* sAh, uint32_t* sAl, int w, float4 a) {
    uint32_t h01 = packbf(a.x, a.y), h23 = packbf(a.z, a.w);
    float fx = a.x - __bfloat162float(__ushort_as_bfloat16((uint16_t)h01));
    float fy = a.y - __bfloat162float(__ushort_as_bfloat16((uint16_t)(h01 >> 16)));
    uint32_t l01 = packbf(fx, fy);
    fx = a.z - __bfloat162float(__ushort_as_bfloat16((uint16_t)h23));
    fy = a.w - __bfloat162float(__ushort_as_bfloat16((uint16_t)(h23 >> 16)));
    uint32_t l23 = packbf(fx, fy);
    sAh[w] = h01; sAh[w + 1] = h23;
    sAl[w] = l01; sAl[w + 1] = l23;
}

// =================== edge GEMM + fused epilogue (A-prefetch pipeline) =======
__global__ void __launch_bounds__(256, 2)
k_edge_gemm(const float* __restrict__ pf, const int* __restrict__ sid) {
    extern __shared__ char smem[];
    uint32_t sbase = (uint32_t)__cvta_generic_to_shared(smem);
    uint32_t* sAh = (uint32_t*)smem;
    uint32_t* sAl = sAh + 128 * LDW;
    uint32_t* sBh = sAl + 128 * LDW;
    uint32_t* sBl = sBh + 128 * LDW;
    int tid = threadIdx.x, wid = tid >> 5, lane = tid & 31;
    int g = lane >> 2, tg = lane & 3;
    int warpM = wid & 1, warpN = wid >> 1;
    int row0 = blockIdx.x * 128;

    uint32_t aoff = a_ldsm_off(lane, warpM);
    uint32_t boff = b_ldsm_off(lane, warpN);
    uint32_t aH = sbase + aoff,            aL = sbase + TILEB + aoff;
    uint32_t bH = sbase + 2 * TILEB + boff, bL = sbase + 3 * TILEB + boff;

    // per-thread A coordinates (fixed across chunks)
    int a_r = tid >> 4;              // rows handled: a_r + 16*it
    int a_cq = tid & 15;             // k quad

    float acc[4][4][4];
#pragma unroll
    for (int mt = 0; mt < 4; mt++)
#pragma unroll
        for (int nt = 0; nt < 4; nt++)
#pragma unroll
            for (int j = 0; j < 4; j++) acc[mt][nt][j] = 0.f;

    // prefetch chunk 0
    float4 pre[8];
#pragma unroll
    for (int it = 0; it < 8; it++) {
        int r = a_r + 16 * it;
        int k = a_cq * 4;
        pre[it] = make_float4(0.f, 0.f, 0.f, 0.f);
        if (k + 3 < EDIM)
            pre[it] = *(const float4*)(pf + (size_t)(row0 + r) * EDIM + k);
    }

    for (int kk = 0; kk < 256; kk += 64) {
        // B copy (LDGs issue first, latency overlaps A convert ALU)
#pragma unroll
        for (int it = 0; it < 4; it++) {
            int idx = tid + it * 256;
            int n = idx >> 3, j = idx & 7;
            const char* srch = (const char*)g_Bh + ((size_t)n * 256 + kk + j * 8) * 2;
            const char* srcl = (const char*)g_Bl + ((size_t)n * 256 + kk + j * 8) * 2;
            *(uint4*)(sBh + n * LDW + j * 4) = *(const uint4*)srch;
            *(uint4*)(sBl + n * LDW + j * 4) = *(const uint4*)srcl;
        }
        // convert prefetched A regs -> smem
#pragma unroll
        for (int it = 0; it < 8; it++) {
            int r = a_r + 16 * it;
            store_split(sAh, sAl, r * LDW + a_cq * 2, pre[it]);
        }
        __syncthreads();
        // prefetch next chunk's A during MMA (hides DRAM latency)
        if (kk < 192) {
#pragma unroll
            for (int it = 0; it < 8; it++) {
                int r = a_r + 16 * it;
                int k = kk + 64 + a_cq * 4;
                pre[it] = make_float4(0.f, 0.f, 0.f, 0.f);
                if (k + 3 < EDIM)
                    pre[it] = *(const float4*)(pf + (size_t)(row0 + r) * EDIM + k);
            }
        }
        int ksmax = (kk == 192) ? 3 : 4;   // k 240..255 is all zero padding
        mma_chunk(aH, aL, bH, bL, acc, ksmax);
        __syncthreads();
    }

    // fused epilogue: y = acc + srcterm[sid[r]], store, BN stats
    float s_loc[4][2], q_loc[4][2];
#pragma unroll
    for (int nt = 0; nt < 4; nt++) {
        s_loc[nt][0] = s_loc[nt][1] = 0.f;
        q_loc[nt][0] = q_loc[nt][1] = 0.f;
    }
#pragma unroll
    for (int mt = 0; mt < 4; mt++) {
        int r0 = row0 + warpM * 64 + mt * 16 + g;
        const float* st0 = g_srcterm + (size_t)sid[r0] * DIM;
        const float* st1 = g_srcterm + (size_t)sid[r0 + 8] * DIM;
#pragma unroll
        for (int nt = 0; nt < 4; nt++) {
            int n = warpN * 32 + nt * 8 + 2 * tg;
            float2 e0 = *(const float2*)(st0 + n);
            float2 e1 = *(const float2*)(st1 + n);
            float y00 = acc[mt][nt][0] + e0.x, y01 = acc[mt][nt][1] + e0.y;
            float y10 = acc[mt][nt][2] + e1.x, y11 = acc[mt][nt][3] + e1.y;
            *(float2*)(g_xg + (size_t)r0 * DIM + n) = make_float2(y00, y01);
            *(float2*)(g_xg + (size_t)(r0 + 8) * DIM + n) = make_float2(y10, y11);
            s_loc[nt][0] += y00 + y10; s_loc[nt][1] += y01 + y11;
            q_loc[nt][0] += y00 * y00 + y10 * y10;
            q_loc[nt][1] += y01 * y01 + y11 * y11;
        }
    }
    __syncthreads();
    float* sS = (float*)smem;
    float* sQ = sS + 128;
    if (tid < 128) { sS[tid] = 0.f; sQ[tid] = 0.f; }
    __syncthreads();
#pragma unroll
    for (int nt = 0; nt < 4; nt++) {
        int n = warpN * 32 + nt * 8 + 2 * tg;
        atomicAdd(&sS[n], s_loc[nt][0]);
        atomicAdd(&sS[n + 1], s_loc[nt][1]);
        atomicAdd(&sQ[n], q_loc[nt][0]);
        atomicAdd(&sQ[n + 1], q_loc[nt][1]);
    }
    __syncthreads();
    if (tid < 128) {
        int bkt = (blockIdx.x & 31) * DIM + tid;
        atomicAdd(&g_psumB[bkt], (double)sS[tid]);
        atomicAdd(&g_psumsqB[bkt], (double)sQ[tid]);
    }
}

// =================== generic node HMMA GEMM =================================
template <int AMODE, int EMODE>
__global__ void __launch_bounds__(256, 2)
k_nmma(const float* __restrict__ A1, const float* __restrict__ A2,
       int M, int Kreal, int Kpad,
       const __nv_bfloat16* __restrict__ Wh, const __nv_bfloat16* __restrict__ Wl,
       long wstr, const float* __restrict__ bias, long bstr,
       float* __restrict__ C, long cstr) {
    int bz = blockIdx.y;
    Wh += (size_t)bz * wstr; Wl += (size_t)bz * wstr;
    bias += (size_t)bz * bstr; C += (size_t)bz * cstr;

    extern __shared__ char smem[];
    uint32_t sbase = (uint32_t)__cvta_generic_to_shared(smem);
    uint32_t* sAh = (uint32_t*)smem;
    uint32_t* sAl = sAh + 128 * LDW;
    uint32_t* sBh = sAl + 128 * LDW;
    uint32_t* sBl = sBh + 128 * LDW;
    int tid = threadIdx.x, wid = tid >> 5, lane = tid & 31;
    int g = lane >> 2, tg = lane & 3;
    int warpM = wid & 1, warpN = wid >> 1;
    int row0 = blockIdx.x * 128;

    uint32_t aoff = a_ldsm_off(lane, warpM);
    uint32_t boff = b_ldsm_off(lane, warpN);
    uint32_t aH = sbase + aoff,            aL = sbase + TILEB + aoff;
    uint32_t bH = sbase + 2 * TILEB + boff, bL = sbase + 3 * TILEB + boff;

    float acc[4][4][4];
#pragma unroll
    for (int mt = 0; mt < 4; mt++)
#pragma unroll
        for (int nt = 0; nt < 4; nt++)
#pragma unroll
            for (int j = 0; j < 4; j++) acc[mt][nt][j] = 0.f;

    for (int kk = 0; kk < Kpad; kk += 64) {
#pragma unroll
        for (int it = 0; it < 8; it++) {
            int idx = tid + it * 256;
            int r = idx >> 4, cq = idx & 15;
            int k = kk + cq * 4;
            int grow = row0 + r;
            float4 a = make_float4(0.f, 0.f, 0.f, 0.f);
            if (grow < M) {
                if (AMODE == 0) {
                    if (k < EDIM) a = *(const float4*)(A1 + (size_t)grow * EDIM + k);
                    else if (k < EDIM + DIM) a = *(const float4*)(A2 + (size_t)grow * DIM + (k - EDIM));
                } else if (AMODE == 1) {
                    int blk = k >> 7;
                    float4 t = *(const float4*)(g_T + ((size_t)(blk * NSRC + grow)) * DIM + (k & 127));
                    float4 ta = *(const float4*)(g_ta + k);
                    float4 tc = *(const float4*)(g_tc + k);
                    a.x = fmaxf(ta.x * t.x + tc.x, 0.f);
                    a.y = fmaxf(ta.y * t.y + tc.y, 0.f);
                    a.z = fmaxf(ta.z * t.z + tc.z, 0.f);
                    a.w = fmaxf(ta.w * t.w + tc.w, 0.f);
                } else {
                    if (k < Kreal) a = *(const float4*)(A1 + (size_t)grow * Kreal + k);
                }
            }
            store_split(sAh, sAl, r * LDW + cq * 2, a);
        }
#pragma unroll
        for (int it = 0; it < 4; it++) {
            int idx = tid + it * 256;
            int n = idx >> 3, j = idx & 7;
            const char* srch = (const char*)Wh + ((size_t)n * Kpad + kk + j * 8) * 2;
            const char* srcl = (const char*)Wl + ((size_t)n * Kpad + kk + j * 8) * 2;
            *(uint4*)(sBh + n * LDW + j * 4) = *(const uint4*)srch;
            *(uint4*)(sBl + n * LDW + j * 4) = *(const uint4*)srcl;
        }
        __syncthreads();
        int rem = (Kreal - kk + 15) >> 4;
        int ksmax = rem < 4 ? rem : 4;
        mma_chunk(aH, aL, bH, bL, acc, ksmax);
        __syncthreads();
    }

    float s_loc[4][2], q_loc[4][2];
    if (EMODE == 2) {
#pragma unroll
        for (int nt = 0; nt < 4; nt++) {
            s_loc[nt][0] = s_loc[nt][1] = 0.f;
            q_loc[nt][0] = q_loc[nt][1] = 0.f;
        }
    }
#pragma unroll
    for (int mt = 0; mt < 4; mt++) {
        int r0 = row0 + warpM * 64 + mt * 16 + g;
        bool v0 = r0 < M, v1 = (r0 + 8) < M;
#pragma unroll
        for (int nt = 0; nt < 4; nt++) {
            int n = warpN * 32 + nt * 8 + 2 * tg;
            float b0 = bias[n], b1 = bias[n + 1];
            float y00 = acc[mt][nt][0] + b0, y01 = acc[mt][nt][1] + b1;
            float y10 = acc[mt][nt][2] + b0, y11 = acc[mt][nt][3] + b1;
            if (EMODE == 1) {
                y00 = fmaxf(y00, 0.f); y01 = fmaxf(y01, 0.f);
                y10 = fmaxf(y10, 0.f); y11 = fmaxf(y11, 0.f);
            }
            if (v0) *(float2*)(C + (size_t)r0 * DIM + n) = make_float2(y00, y01);
            if (v1) *(float2*)(C + (size_t)(r0 + 8) * DIM + n) = make_float2(y10, y11);
            if (EMODE == 2) {
                if (v0) { s_loc[nt][0] += y00; s_loc[nt][1] += y01;
                          q_loc[nt][0] += y00 * y00; q_loc[nt][1] += y01 * y01; }
                if (v1) { s_loc[nt][0] += y10; s_loc[nt][1] += y11;
                          q_loc[nt][0] += y10 * y10; q_loc[nt][1] += y11 * y11; }
            }
        }
    }
    if (EMODE == 2) {
        __syncthreads();
        float* sS = (float*)smem;
        float* sQ = sS + 128;
        if (tid < 128) { sS[tid] = 0.f; sQ[tid] = 0.f; }
        __syncthreads();
#pragma unroll
        for (int nt = 0; nt < 4; nt++) {
            int n = warpN * 32 + nt * 8 + 2 * tg;
            atomicAdd(&sS[n], s_loc[nt][0]);
            atomicAdd(&sS[n + 1], s_loc[nt][1]);
            atomicAdd(&sQ[n], q_loc[nt][0]);
            atomicAdd(&sQ[n + 1], q_loc[nt][1]);
        }
        __syncthreads();
        if (tid < 128) {
            atomicAdd(&g_tsum[bz * DIM + tid], (double)sS[tid]);
            atomicAdd(&g_tsumsq[bz * DIM + tid], (double)sQ[tid]);
        }
    }
}

// ---------------- BN coefficient finalization -------------------------------
__global__ void k_coef1(const float* __restrict__ bng, const float* __restrict__ bnb,
                        const float* __restrict__ psb, const float* __restrict__ ptb) {
    int t = blockIdx.x * blockDim.x + threadIdx.x;
    if (t < 3 * DIM) {
        double mean = g_tsum[t] / NSRC;
        double var = g_tsumsq[t] / NSRC - mean * mean;
        float a = bng[t] * rsqrtf((float)var + BN_EPS);
        g_ta[t] = a;
        g_tc[t] = bnb[t] - a * (float)mean;
    }
    if (t < DIM) g_combB[t] = psb[t] + ptb[t];
}

__global__ void k_coef2(const float* __restrict__ peg, const float* __restrict__ peb) {
    int t = threadIdx.x;
    double s = 0.0, q = 0.0;
#pragma unroll
    for (int b2 = 0; b2 < 32; b2++) {
        s += g_psumB[b2 * DIM + t];
        q += g_psumsqB[b2 * DIM + t];
    }
    double mean = s / NEDGE;
    double var = q / NEDGE - mean * mean;
    float a = peg[t] * rsqrtf((float)var + BN_EPS);
    g_peA[t] = a;
    g_peC[t] = peb[t] - a * (float)mean;
}

// ---------------- scores (y already includes srcterm) ------------------------
__global__ void k_scores(const float* __restrict__ sw) {
    int w = (blockIdx.x * blockDim.x + threadIdx.x) >> 5;
    int lane = threadIdx.x & 31;
    int e0 = w * 64;
    float a[4], c4[4], wv[4];
#pragma unroll
    for (int j = 0; j < 4; j++) {
        int cc = lane + 32 * j;
        a[j] = g_peA[cc]; c4[j] = g_peC[cc]; wv[j] = sw[cc];
    }
    for (int e = e0; e < e0 + 64; e++) {
        const float* yr = g_xg + (size_t)e * DIM;
        float p = 0.f;
#pragma unroll
        for (int j = 0; j < 4; j++) {
            float v = a[j] * yr[lane + 32 * j] + c4[j];
            v = (v > 0.f) ? v : 0.f;
            p += v * wv[j];
        }
#pragma unroll
        for (int o = 16; o; o >>= 1) p += __shfl_xor_sync(0xffffffffu, p, o);
        if (lane == 0) g_scores[e] = p;
    }
}

// ---------------- top-k ------------------------------------------------------
__device__ __forceinline__ bool kbetter(float s1, int i1, float s2, int i2) {
    return (s1 > s2) || (s1 == s2 && i1 < i2);
}
__device__ __forceinline__ void top_insert(float* bs, int* bi, float v, int e) {
    if (!kbetter(v, e, bs[TOPN - 1], bi[TOPN - 1])) return;
    int p = TOPN - 1;
    while (p > 0 && kbetter(v, e, bs[p - 1], bi[p - 1])) {
        bs[p] = bs[p - 1]; bi[p] = bi[p - 1]; p--;
    }
    bs[p] = v; bi[p] = e;
}

__global__ void k_top_a() {
    float bs[TOPN]; int bi[TOPN];
#pragma unroll
    for (int j = 0; j < TOPN; j++) { bs[j] = -1e30f; bi[j] = 0x7fffffff; }
    int t = blockIdx.x * 256 + threadIdx.x;
    for (int e = t; e < NEDGE; e += 128 * 256) {
        top_insert(bs, bi, g_scores[e], e);
    }
    __shared__ float ss[256 * TOPN];
    __shared__ int si[256 * TOPN];
#pragma unroll
    for (int j = 0; j < TOPN; j++) {
        ss[threadIdx.x * TOPN + j] = bs[j];
        si[threadIdx.x * TOPN + j] = bi[j];
    }
    __syncthreads();
    if (threadIdx.x == 0) {
        float cs[TOPN]; int ci[TOPN];
#pragma unroll
        for (int j = 0; j < TOPN; j++) { cs[j] = -1e30f; ci[j] = 0x7fffffff; }
        for (int k = 0; k < 256 * TOPN; k++) top_insert(cs, ci, ss[k], si[k]);
        for (int j = 0; j < TOPN; j++) {
            g_cs[blockIdx.x * TOPN + j] = cs[j];
            g_ci[blockIdx.x * TOPN + j] = ci[j];
        }
    }
}

__global__ void k_top_b(float* __restrict__ out) {
    if (threadIdx.x == 0) {
        float cs[TOPN]; int ci[TOPN];
#pragma unroll
        for (int j = 0; j < TOPN; j++) { cs[j] = -1e30f; ci[j] = 0x7fffffff; }
        for (int k = 0; k < 128 * TOPN; k++) top_insert(cs, ci, g_cs[k], g_ci[k]);
        for (int j = 0; j < TOPN; j++) {
            out[(size_t)NSRC * DIM + j] = cs[j];
            out[(size_t)NSRC * DIM + TOPN + j] = (float)ci[j];
        }
    }
}

// ---------------- host entry -------------------------------------------------
extern "C" void kernel_launch(void* const* d_in, const int* in_sizes, int n_in,
                              void* d_out, int out_size) {
    bool dictorder = (in_sizes[2] == NEDGE);
    const float* paths = (const float*)d_in[0];
    const float* pf    = (const float*)d_in[1];
    const int*   sid   = (const int*)d_in[dictorder ? 2 : 19];
    int b = dictorder ? 3 : 2;
    const float* cew = (const float*)d_in[b + 0];
    const float* ceb = (const float*)d_in[b + 1];
    const float* w1  = (const float*)d_in[b + 2];
    const float* bng = (const float*)d_in[b + 3];
    const float* bnb = (const float*)d_in[b + 4];
    const float* w2  = (const float*)d_in[b + 5];
    const float* l1W = (const float*)d_in[b + 6];
    const float* l1b = (const float*)d_in[b + 7];
    const float* l2W = (const float*)d_in[b + 8];
    const float* l2b = (const float*)d_in[b + 9];
    const float* psW = (const float*)d_in[b + 10];
    const float* psb = (const float*)d_in[b + 11];
    const float* ptW = (const float*)d_in[b + 12];
    const float* ptb = (const float*)d_in[b + 13];
    const float* peg = (const float*)d_in[b + 14];
    const float* peb = (const float*)d_in[b + 15];
    const float* sw  = (const float*)d_in[b + 16];
    float* out = (float*)d_out;

    void *p_agg, *p_Wc, *p_Wei1, *p_T, *p_h2, *p_srcterm, *p_cvec, *p_combB;
    void *p_Wbh, *p_Wbl, *p_Wch, *p_Wcl, *p_l2h, *p_l2l, *p_psh, *p_psl;
    cudaGetSymbolAddress(&p_agg, g_agg);
    cudaGetSymbolAddress(&p_Wc, g_Wc);
    cudaGetSymbolAddress(&p_Wei1, g_Wei1);
    cudaGetSymbolAddress(&p_T, g_T);
    cudaGetSymbolAddress(&p_h2, g_h2);
    cudaGetSymbolAddress(&p_srcterm, g_srcterm);
    cudaGetSymbolAddress(&p_cvec, g_cvec);
    cudaGetSymbolAddress(&p_combB, g_combB);
    cudaGetSymbolAddress(&p_Wbh, g_Wbh);
    cudaGetSymbolAddress(&p_Wbl, g_Wbl);
    cudaGetSymbolAddress(&p_Wch, g_Wch);
    cudaGetSymbolAddress(&p_Wcl, g_Wcl);
    cudaGetSymbolAddress(&p_l2h, g_l2h);
    cudaGetSymbolAddress(&p_l2l, g_l2l);
    cudaGetSymbolAddress(&p_psh, g_psh);
    cudaGetSymbolAddress(&p_psl, g_psl);
    const __nv_bfloat16* Wbh = (const __nv_bfloat16*)p_Wbh;
    const __nv_bfloat16* Wbl = (const __nv_bfloat16*)p_Wbl;
    const __nv_bfloat16* Wch = (const __nv_bfloat16*)p_Wch;
    const __nv_bfloat16* Wcl = (const __nv_bfloat16*)p_Wcl;
    const __nv_bfloat16* l2h = (const __nv_bfloat16*)p_l2h;
    const __nv_bfloat16* l2l = (const __nv_bfloat16*)p_l2l;
    const __nv_bfloat16* psh = (const __nv_bfloat16*)p_psh;
    const __nv_bfloat16* psl = (const __nv_bfloat16*)p_psl;

    cudaFuncSetAttribute(k_edge_gemm, cudaFuncAttributeMaxDynamicSharedMemorySize, EG_SMEM);
    cudaFuncSetAttribute(k_nmma<0, 2>, cudaFuncAttributeMaxDynamicSharedMemorySize, EG_SMEM);
    cudaFuncSetAttribute(k_nmma<1, 1>, cudaFuncAttributeMaxDynamicSharedMemorySize, EG_SMEM);
    cudaFuncSetAttribute(k_nmma<2, 0>, cudaFuncAttributeMaxDynamicSharedMemorySize, EG_SMEM);

    const int NODE_BLKS = (NSRC + 127) / 128;   // 79

    k_reset<<<40, 256>>>();
    k_hist<<<(NEDGE + 255) / 256, 256>>>(sid);
    k_scan<<<1, 1024>>>();
    k_scatter<<<(NEDGE + 255) / 256, 256>>>(sid);
    k_prepB<<<128, 256>>>(ptW);
    k_agg<<<(NSRC * 32 + 255) / 256, 256>>>(pf);

    gemm128<<<dim3(1, 3), 256>>>(w2, DIM, DIM, DIM, (long)DIM * DIM,
                                 l1W, (long)DIM * DIM, (float*)p_Wc, (long)DIM * DIM);
    gemm128<<<dim3(2, 3), 256>>>(cew, EDIM, DIM, DIM, (long)EDIM * DIM,
                                 w1, (long)DIM * DIM, (float*)p_Wei1, (long)EDIM * DIM);
    k_cvec<<<3, 128>>>(ceb, w1);

    k_prepWbig<<<dim3(192, 3), 256>>>(w1);
    k_prepWgen<<<192, 256>>>((const float*)p_Wc, (__nv_bfloat16*)p_Wch,
                             (__nv_bfloat16*)p_Wcl, 384, 384);
    k_prepWgen<<<64, 256>>>(l2W, (__nv_bfloat16*)p_l2h, (__nv_bfloat16*)p_l2l, 128, 128);
    k_prepWgen<<<64, 256>>>(psW, (__nv_bfloat16*)p_psh, (__nv_bfloat16*)p_psl, 128, 128);

    k_nmma<0, 2><<<dim3(NODE_BLKS, 3), 256, EG_SMEM>>>(
        (const float*)p_agg, paths, NSRC, EDIM + DIM, 384,
        Wbh, Wbl, (long)128 * 384, (const float*)p_cvec, DIM,
        (float*)p_T, (long)NSRC * DIM);
    k_coef1<<<2, 256>>>(bng, bnb, psb, ptb);

    k_nmma<1, 1><<<dim3(NODE_BLKS, 1), 256, EG_SMEM>>>(
        nullptr, nullptr, NSRC, 384, 384,
        Wch, Wcl, 0L, l1b, 0L, (float*)p_h2, 0L);
    k_nmma<2, 0><<<dim3(NODE_BLKS, 1), 256, EG_SMEM>>>(
        (const float*)p_h2, nullptr, NSRC, 128, 128,
        l2h, l2l, 0L, l2b, 0L, out, 0L);
    k_nmma<2, 0><<<dim3(NODE_BLKS, 1), 256, EG_SMEM>>>(
        out, nullptr, NSRC, 128, 128,
        psh, psl, 0L, (const float*)p_combB, 0L, (float*)p_srcterm, 0L);

    // edge GEMM (HMMA split-bf16, ldmatrix + A-prefetch pipeline) fused epilogue
    k_edge_gemm<<<NEDGE / 128, 256, EG_SMEM>>>(pf, sid);

    k_coef2<<<1, 128>>>(peg, peb);
    k_scores<<<NEDGE / 512, 256>>>(sw);
    k_top_a<<<128, 256>>>();
    k_top_b<<<1, 32>>>(out);
}

// round 15
// speedup vs baseline: 1.0333x; 1.0333x over previous
#include <cuda_runtime.h>
#include <cuda_bf16.h>
#include <math.h>
#include <stdint.h>

#define NSRC 10000
#define NEDGE 320000
#define DIM 128
#define EDIM 236
#define TOPN 6
#define BN_EPS 1e-5f

// ---------------- scratch (device globals; no allocation allowed) ----------
__device__ float  g_agg[(size_t)NSRC * EDIM];
__device__ float  g_xg[(size_t)NEDGE * DIM];         // holds y = xg + srcterm[sid]
__device__ float  g_srcterm[(size_t)NSRC * DIM];
__device__ float  g_T[(size_t)3 * NSRC * DIM];
__device__ float  g_Wc[3 * DIM * DIM];
__device__ float  g_Wei1[3 * EDIM * DIM];
__device__ float  g_cvec[3 * DIM];
__device__ float  g_scores[NEDGE];
__device__ int    g_cnt[NSRC];
__device__ int    g_off[NSRC + 1];
__device__ int    g_cur[NSRC];
__device__ int    g_order[NEDGE];
__device__ double g_tsum[3 * DIM], g_tsumsq[3 * DIM];
__device__ double g_psumB[32 * DIM], g_psumsqB[32 * DIM];
__device__ float  g_ta[3 * DIM], g_tc[3 * DIM];
__device__ float  g_peA[DIM], g_peC[DIM];
__device__ float  g_combB[DIM];
__device__ float  g_cs[128 * TOPN];
__device__ int    g_ci[128 * TOPN];
// pre-split bf16 weights, n-major [n][Kpad]
__device__ __nv_bfloat16 g_Bh[128 * 256],  g_Bl[128 * 256];
__device__ __nv_bfloat16 g_Wbh[3 * 128 * 384], g_Wbl[3 * 128 * 384];
__device__ __nv_bfloat16 g_Wch[128 * 384], g_Wcl[128 * 384];
__device__ __nv_bfloat16 g_l2h[128 * 128], g_l2l[128 * 128];
__device__ __nv_bfloat16 g_psh[128 * 128], g_psl[128 * 128];

// ---------------- small utility kernels ------------------------------------
__global__ void k_reset() {
    int t = blockIdx.x * blockDim.x + threadIdx.x;
    if (t < NSRC) g_cnt[t] = 0;
    if (t < 3 * DIM) { g_tsum[t] = 0.0; g_tsumsq[t] = 0.0; }
    if (t < 32 * DIM) { g_psumB[t] = 0.0; g_psumsqB[t] = 0.0; }
}

__global__ void k_hist(const int* __restrict__ sid) {
    int e = blockIdx.x * blockDim.x + threadIdx.x;
    if (e < NEDGE) atomicAdd(&g_cnt[sid[e]], 1);
}

__global__ void k_scan() {
    __shared__ int s[1024];
    int t = threadIdx.x;
    int base = t * 10;
    int loc[10];
    int acc = 0;
#pragma unroll
    for (int j = 0; j < 10; j++) {
        int idx = base + j;
        int v = (idx < NSRC) ? g_cnt[idx] : 0;
        loc[j] = acc; acc += v;
    }
    s[t] = acc;
    __syncthreads();
    for (int off = 1; off < 1024; off <<= 1) {
        int v = (t >= off) ? s[t - off] : 0;
        __syncthreads();
        s[t] += v;
        __syncthreads();
    }
    int pre = (t > 0) ? s[t - 1] : 0;
#pragma unroll
    for (int j = 0; j < 10; j++) {
        int idx = base + j;
        if (idx < NSRC) { g_off[idx] = pre + loc[j]; g_cur[idx] = pre + loc[j]; }
    }
    if (t == 0) g_off[NSRC] = NEDGE;
}

__global__ void k_scatter(const int* __restrict__ sid) {
    int e = blockIdx.x * blockDim.x + threadIdx.x;
    if (e < NEDGE) {
        int p = atomicAdd(&g_cur[sid[e]], 1);
        g_order[p] = e;
    }
}

__device__ __forceinline__ void splitbf(float v, __nv_bfloat16& h, __nv_bfloat16& l) {
    h = __float2bfloat16(v);
    l = __float2bfloat16(v - __bfloat162float(h));
}

__global__ void k_prepB(const float* __restrict__ ptW) {
    int idx = blockIdx.x * 256 + threadIdx.x;
    if (idx >= 128 * 256) return;
    int k = idx >> 7, n = idx & 127;
    float b = (k < EDIM) ? ptW[(size_t)k * DIM + n] : 0.f;
    __nv_bfloat16 h, l; splitbf(b, h, l);
    g_Bh[n * 256 + k] = h;
    g_Bl[n * 256 + k] = l;
}

__global__ void k_prepWbig(const float* __restrict__ w1) {
    int i = blockIdx.y;
    int idx = blockIdx.x * 256 + threadIdx.x;
    int n = idx / 384, k = idx % 384;
    float v = 0.f;
    if (k < EDIM) v = g_Wei1[i * EDIM * DIM + k * DIM + n];
    else if (k < EDIM + DIM) v = w1[i * DIM * DIM + (k - EDIM) * DIM + n];
    __nv_bfloat16 h, l; splitbf(v, h, l);
    g_Wbh[i * 128 * 384 + n * 384 + k] = h;
    g_Wbl[i * 128 * 384 + n * 384 + k] = l;
}

__global__ void k_prepWgen(const float* __restrict__ src, __nv_bfloat16* __restrict__ dh,
                           __nv_bfloat16* __restrict__ dl, int K, int Kpad) {
    int idx = blockIdx.x * 256 + threadIdx.x;
    if (idx >= 128 * Kpad) return;
    int n = idx / Kpad, k = idx % Kpad;
    float v = (k < K) ? src[(size_t)k * DIM + n] : 0.f;
    __nv_bfloat16 h, l; splitbf(v, h, l);
    dh[n * Kpad + k] = h;
    dl[n * Kpad + k] = l;
}

__global__ void k_cvec(const float* __restrict__ ceb, const float* __restrict__ w1) {
    int i = blockIdx.x, n = threadIdx.x;
    float s = 0.f;
    for (int k = 0; k < DIM; k++)
        s += ceb[i * DIM + k] * w1[i * DIM * DIM + k * DIM + n];
    g_cvec[i * DIM + n] = s;
}

__global__ void k_agg(const float* __restrict__ pf) {
    int w = (blockIdx.x * blockDim.x + threadIdx.x) >> 5;
    int lane = threadIdx.x & 31;
    if (w >= NSRC) return;
    float4 a0 = make_float4(0.f, 0.f, 0.f, 0.f);
    float4 a1 = make_float4(0.f, 0.f, 0.f, 0.f);
    int s = g_off[w], e2 = g_off[w + 1];
    for (int p = s; p < e2; p++) {
        const float4* r = (const float4*)(pf + (size_t)g_order[p] * EDIM);
        float4 v = __ldg(r + lane);
        a0.x += fmaxf(v.x, 0.f); a0.y += fmaxf(v.y, 0.f);
        a0.z += fmaxf(v.z, 0.f); a0.w += fmaxf(v.w, 0.f);
        if (lane < 27) {
            float4 v2 = __ldg(r + 32 + lane);
            a1.x += fmaxf(v2.x, 0.f); a1.y += fmaxf(v2.y, 0.f);
            a1.z += fmaxf(v2.z, 0.f); a1.w += fmaxf(v2.w, 0.f);
        }
    }
    float4* outp = (float4*)(g_agg + (size_t)w * EDIM);
    outp[lane] = a0;
    if (lane < 27) outp[32 + lane] = a1;
}

// ---------------- small fp32 GEMM (C = A@W), batched over blockIdx.y --------
__global__ void __launch_bounds__(256)
gemm128(const float* __restrict__ A, int M, int K, int lda, long astr,
        const float* __restrict__ W, long wstr,
        float* __restrict__ C, long cstr) {
    int bz = blockIdx.y;
    A += (size_t)bz * astr;
    W += (size_t)bz * wstr;
    C += (size_t)bz * cstr;

    __shared__ float sA[8][128];
    __shared__ float sW[8][128];
    int tid = threadIdx.x;
    int row0 = blockIdx.x * 128;
    int tx = tid & 15, ty = tid >> 4;
    float acc[8][8];
#pragma unroll
    for (int i = 0; i < 8; i++)
#pragma unroll
        for (int j = 0; j < 8; j++) acc[i][j] = 0.f;

    int ar = tid >> 1;
    int ac = (tid & 1) * 4;
    int wk = (tid * 4) >> 7;
    int wc = (tid * 4) & 127;

    for (int kk = 0; kk < K; kk += 8) {
        float4 av = make_float4(0.f, 0.f, 0.f, 0.f);
        int grow = row0 + ar;
        if (grow < M) {
            int k = kk + ac;
            if (k + 3 < K) {
                av = *(const float4*)(A + (size_t)grow * lda + k);
            } else {
#pragma unroll
                for (int j = 0; j < 4; j++) {
                    int kj = k + j;
                    ((float*)&av)[j] = (kj < K) ? A[(size_t)grow * lda + kj] : 0.f;
                }
            }
        }
        sA[ac + 0][ar] = av.x; sA[ac + 1][ar] = av.y;
        sA[ac + 2][ar] = av.z; sA[ac + 3][ar] = av.w;

        float4 wv = make_float4(0.f, 0.f, 0.f, 0.f);
        if (kk + wk < K) wv = *(const float4*)(W + (size_t)(kk + wk) * 128 + wc);
        *(float4*)&sW[wk][wc] = wv;
        __syncthreads();

#pragma unroll
        for (int k = 0; k < 8; k++) {
            float4 a0 = *(float4*)&sA[k][ty * 8];
            float4 a1 = *(float4*)&sA[k][ty * 8 + 4];
            float4 b0 = *(float4*)&sW[k][tx * 8];
            float4 b1 = *(float4*)&sW[k][tx * 8 + 4];
            float ra[8] = {a0.x, a0.y, a0.z, a0.w, a1.x, a1.y, a1.z, a1.w};
            float rb[8] = {b0.x, b0.y, b0.z, b0.w, b1.x, b1.y, b1.z, b1.w};
#pragma unroll
            for (int i = 0; i < 8; i++)
#pragma unroll
                for (int j = 0; j < 8; j++) acc[i][j] += ra[i] * rb[j];
        }
        __syncthreads();
    }
#pragma unroll
    for (int i = 0; i < 8; i++) {
        int row = row0 + ty * 8 + i;
        if (row < M)
#pragma unroll
            for (int j = 0; j < 8; j++)
                C[(size_t)row * DIM + tx * 8 + j] = acc[i][j];
    }
}

// =================== shared HMMA split-bf16 machinery =======================
#define LDE 72
#define LDW 36
#define ROWB 144                       // bytes per smem row
#define TILEB (128 * ROWB)             // 18432 bytes
#define EG_SMEM (4 * TILEB)            // edge kernel: Ah, Al, Bh, Bl
#define NF_SMEM (6 * TILEB)            // fused node kernel: A0h,A0l,A1h,A1l,Bh,Bl

__device__ __forceinline__ void mma16816(float* c, const uint32_t* a, const uint32_t* b) {
    asm volatile(
        "mma.sync.aligned.m16n8k16.row.col.f32.bf16.bf16.f32 "
        "{%0,%1,%2,%3}, {%4,%5,%6,%7}, {%8,%9}, {%0,%1,%2,%3};"
        : "+f"(c[0]), "+f"(c[1]), "+f"(c[2]), "+f"(c[3])
        : "r"(a[0]), "r"(a[1]), "r"(a[2]), "r"(a[3]), "r"(b[0]), "r"(b[1]));
}
__device__ __forceinline__ void ldsm4(uint32_t* r, uint32_t a) {
    asm volatile("ldmatrix.sync.aligned.m8n8.x4.shared.b16 {%0,%1,%2,%3}, [%4];"
                 : "=r"(r[0]), "=r"(r[1]), "=r"(r[2]), "=r"(r[3]) : "r"(a));
}
__device__ __forceinline__ uint32_t packbf(float x, float y) {
    union { __nv_bfloat162 b; uint32_t u; } c;
    c.b = __float22bfloat162_rn(make_float2(x, y));
    return c.u;
}
__device__ __forceinline__ void split_pair(float y0, float y1, uint32_t& h, uint32_t& l) {
    h = packbf(y0, y1);
    float r0 = y0 - __bfloat162float(__ushort_as_bfloat16((uint16_t)h));
    float r1 = y1 - __bfloat162float(__ushort_as_bfloat16((uint16_t)(h >> 16)));
    l = packbf(r0, r1);
}

// lane-specific ldmatrix base offsets (bytes) within a tile buffer
__device__ __forceinline__ uint32_t a_ldsm_off(int lane, int warpM) {
    int row = warpM * 64 + (lane & 7) + ((lane >> 3) & 1) * 8;
    return (uint32_t)row * ROWB + (uint32_t)((lane >> 4) & 1) * 16;
}
__device__ __forceinline__ uint32_t b_ldsm_off(int lane, int warpN) {
    int row = warpN * 32 + ((lane >> 4) & 1) * 8 + (lane & 7);
    return (uint32_t)row * ROWB + (uint32_t)((lane >> 3) & 1) * 16;
}

__device__ __forceinline__ void mma_chunk(uint32_t aH, uint32_t aL,
                                          uint32_t bH, uint32_t bL,
                                          float acc[4][4][4], int ksmax) {
    for (int ks = 0; ks < ksmax; ks++) {
        uint32_t kb = (uint32_t)ks * 32;
        uint32_t bh[8], bl[8];
        ldsm4(&bh[0], bH + kb);
        ldsm4(&bh[4], bH + 16 * ROWB + kb);
        ldsm4(&bl[0], bL + kb);
        ldsm4(&bl[4], bL + 16 * ROWB + kb);
#pragma unroll
        for (int mt = 0; mt < 4; mt++) {
            uint32_t ah[4], al[4];
            ldsm4(ah, aH + (uint32_t)mt * 16 * ROWB + kb);
            ldsm4(al, aL + (uint32_t)mt * 16 * ROWB + kb);
#pragma unroll
            for (int nt = 0; nt < 4; nt++) {
                mma16816(acc[mt][nt], ah, &bh[nt * 2]);
                mma16816(acc[mt][nt], ah, &bl[nt * 2]);
                mma16816(acc[mt][nt], al, &bh[nt * 2]);
            }
        }
    }
}

__device__ __forceinline__ void store_split(uint32_t* sAh, uint32_t* sAl, int w, float4 a) {
    uint32_t h01 = packbf(a.x, a.y), h23 = packbf(a.z, a.w);
    float fx = a.x - __bfloat162float(__ushort_as_bfloat16((uint16_t)h01));
    float fy = a.y - __bfloat162float(__ushort_as_bfloat16((uint16_t)(h01 >> 16)));
    uint32_t l01 = packbf(fx, fy);
    fx = a.z - __bfloat162float(__ushort_as_bfloat16((uint16_t)h23));
    fy = a.w - __bfloat162float(__ushort_as_bfloat16((uint16_t)(h23 >> 16)));
    uint32_t l23 = packbf(fx, fy);
    sAh[w] = h01; sAh[w + 1] = h23;
    sAl[w] = l01; sAl[w + 1] = l23;
}

// =================== edge GEMM + fused epilogue (R12-proven) ================
__global__ void __launch_bounds__(256, 2)
k_edge_gemm(const float* __restrict__ pf, const int* __restrict__ sid) {
    extern __shared__ char smem[];
    uint32_t sbase = (uint32_t)__cvta_generic_to_shared(smem);
    uint32_t* sAh = (uint32_t*)smem;
    uint32_t* sAl = sAh + 128 * LDW;
    uint32_t* sBh = sAl + 128 * LDW;
    uint32_t* sBl = sBh + 128 * LDW;
    int tid = threadIdx.x, wid = tid >> 5, lane = tid & 31;
    int g = lane >> 2, tg = lane & 3;
    int warpM = wid & 1, warpN = wid >> 1;
    int row0 = blockIdx.x * 128;

    uint32_t aoff = a_ldsm_off(lane, warpM);
    uint32_t boff = b_ldsm_off(lane, warpN);
    uint32_t aH = sbase + aoff,            aL = sbase + TILEB + aoff;
    uint32_t bH = sbase + 2 * TILEB + boff, bL = sbase + 3 * TILEB + boff;

    float acc[4][4][4];
#pragma unroll
    for (int mt = 0; mt < 4; mt++)
#pragma unroll
        for (int nt = 0; nt < 4; nt++)
#pragma unroll
            for (int j = 0; j < 4; j++) acc[mt][nt][j] = 0.f;

    for (int kk = 0; kk < 256; kk += 64) {
#pragma unroll
        for (int it = 0; it < 8; it++) {
            int idx = tid + it * 256;
            int r = idx >> 4, cq = idx & 15;
            int k = kk + cq * 4;
            float4 a = make_float4(0.f, 0.f, 0.f, 0.f);
            if (k + 3 < EDIM)
                a = *(const float4*)(pf + (size_t)(row0 + r) * EDIM + k);
            store_split(sAh, sAl, r * LDW + cq * 2, a);
        }
#pragma unroll
        for (int it = 0; it < 4; it++) {
            int idx = tid + it * 256;
            int n = idx >> 3, j = idx & 7;
            const char* srch = (const char*)g_Bh + ((size_t)n * 256 + kk + j * 8) * 2;
            const char* srcl = (const char*)g_Bl + ((size_t)n * 256 + kk + j * 8) * 2;
            *(uint4*)(sBh + n * LDW + j * 4) = *(const uint4*)srch;
            *(uint4*)(sBl + n * LDW + j * 4) = *(const uint4*)srcl;
        }
        __syncthreads();
        int ksmax = (kk == 192) ? 3 : 4;   // k 240..255 is all zero padding
        mma_chunk(aH, aL, bH, bL, acc, ksmax);
        __syncthreads();
    }

    // fused epilogue: y = acc + srcterm[sid[r]], store, BN stats
    float s_loc[4][2], q_loc[4][2];
#pragma unroll
    for (int nt = 0; nt < 4; nt++) {
        s_loc[nt][0] = s_loc[nt][1] = 0.f;
        q_loc[nt][0] = q_loc[nt][1] = 0.f;
    }
#pragma unroll
    for (int mt = 0; mt < 4; mt++) {
        int r0 = row0 + warpM * 64 + mt * 16 + g;
        const float* st0 = g_srcterm + (size_t)sid[r0] * DIM;
        const float* st1 = g_srcterm + (size_t)sid[r0 + 8] * DIM;
#pragma unroll
        for (int nt = 0; nt < 4; nt++) {
            int n = warpN * 32 + nt * 8 + 2 * tg;
            float2 e0 = *(const float2*)(st0 + n);
            float2 e1 = *(const float2*)(st1 + n);
            float y00 = acc[mt][nt][0] + e0.x, y01 = acc[mt][nt][1] + e0.y;
            float y10 = acc[mt][nt][2] + e1.x, y11 = acc[mt][nt][3] + e1.y;
            *(float2*)(g_xg + (size_t)r0 * DIM + n) = make_float2(y00, y01);
            *(float2*)(g_xg + (size_t)(r0 + 8) * DIM + n) = make_float2(y10, y11);
            s_loc[nt][0] += y00 + y10; s_loc[nt][1] += y01 + y11;
            q_loc[nt][0] += y00 * y00 + y10 * y10;
            q_loc[nt][1] += y01 * y01 + y11 * y11;
        }
    }
    __syncthreads();
    float* sS = (float*)smem;
    float* sQ = sS + 128;
    if (tid < 128) { sS[tid] = 0.f; sQ[tid] = 0.f; }
    __syncthreads();
#pragma unroll
    for (int nt = 0; nt < 4; nt++) {
        int n = warpN * 32 + nt * 8 + 2 * tg;
        atomicAdd(&sS[n], s_loc[nt][0]);
        atomicAdd(&sS[n + 1], s_loc[nt][1]);
        atomicAdd(&sQ[n], q_loc[nt][0]);
        atomicAdd(&sQ[n + 1], q_loc[nt][1]);
    }
    __syncthreads();
    if (tid < 128) {
        int bkt = (blockIdx.x & 31) * DIM + tid;
        atomicAdd(&g_psumB[bkt], (double)sS[tid]);
        atomicAdd(&g_psumsqB[bkt], (double)sQ[tid]);
    }
}

// =================== T_cat node GEMM (A = [agg|paths], BN stats) ============
__global__ void __launch_bounds__(256, 2)
k_ncat(const float* __restrict__ A1, const float* __restrict__ A2,
       const __nv_bfloat16* __restrict__ Wh, const __nv_bfloat16* __restrict__ Wl,
       const float* __restrict__ bias, float* __restrict__ C) {
    int bz = blockIdx.y;
    Wh += (size_t)bz * 128 * 384; Wl += (size_t)bz * 128 * 384;
    bias += (size_t)bz * DIM; C += (size_t)bz * NSRC * DIM;

    extern __shared__ char smem[];
    uint32_t sbase = (uint32_t)__cvta_generic_to_shared(smem);
    uint32_t* sAh = (uint32_t*)smem;
    uint32_t* sAl = sAh + 128 * LDW;
    uint32_t* sBh = sAl + 128 * LDW;
    uint32_t* sBl = sBh + 128 * LDW;
    int tid = threadIdx.x, wid = tid >> 5, lane = tid & 31;
    int g = lane >> 2, tg = lane & 3;
    int warpM = wid & 1, warpN = wid >> 1;
    int row0 = blockIdx.x * 128;

    uint32_t aoff = a_ldsm_off(lane, warpM);
    uint32_t boff = b_ldsm_off(lane, warpN);
    uint32_t aH = sbase + aoff,            aL = sbase + TILEB + aoff;
    uint32_t bH = sbase + 2 * TILEB + boff, bL = sbase + 3 * TILEB + boff;

    float acc[4][4][4];
#pragma unroll
    for (int mt = 0; mt < 4; mt++)
#pragma unroll
        for (int nt = 0; nt < 4; nt++)
#pragma unroll
            for (int j = 0; j < 4; j++) acc[mt][nt][j] = 0.f;

    for (int kk = 0; kk < 384; kk += 64) {
#pragma unroll
        for (int it = 0; it < 8; it++) {
            int idx = tid + it * 256;
            int r = idx >> 4, cq = idx & 15;
            int k = kk + cq * 4;
            int grow = row0 + r;
            float4 a = make_float4(0.f, 0.f, 0.f, 0.f);
            if (grow < NSRC) {
                if (k < EDIM) a = *(const float4*)(A1 + (size_t)grow * EDIM + k);
                else if (k < EDIM + DIM) a = *(const float4*)(A2 + (size_t)grow * DIM + (k - EDIM));
            }
            store_split(sAh, sAl, r * LDW + cq * 2, a);
        }
#pragma unroll
        for (int it = 0; it < 4; it++) {
            int idx = tid + it * 256;
            int n = idx >> 3, j = idx & 7;
            const char* srch = (const char*)Wh + ((size_t)n * 384 + kk + j * 8) * 2;
            const char* srcl = (const char*)Wl + ((size_t)n * 384 + kk + j * 8) * 2;
            *(uint4*)(sBh + n * LDW + j * 4) = *(const uint4*)srch;
            *(uint4*)(sBl + n * LDW + j * 4) = *(const uint4*)srcl;
        }
        __syncthreads();
        int rem = (364 - kk + 15) >> 4;          // Kreal = 364
        int ksmax = rem < 4 ? rem : 4;
        mma_chunk(aH, aL, bH, bL, acc, ksmax);
        __syncthreads();
    }

    float s_loc[4][2], q_loc[4][2];
#pragma unroll
    for (int nt = 0; nt < 4; nt++) {
        s_loc[nt][0] = s_loc[nt][1] = 0.f;
        q_loc[nt][0] = q_loc[nt][1] = 0.f;
    }
#pragma unroll
    for (int mt = 0; mt < 4; mt++) {
        int r0 = row0 + warpM * 64 + mt * 16 + g;
        bool v0 = r0 < NSRC, v1 = (r0 + 8) < NSRC;
#pragma unroll
        for (int nt = 0; nt < 4; nt++) {
            int n = warpN * 32 + nt * 8 + 2 * tg;
            float b0 = bias[n], b1 = bias[n + 1];
            float y00 = acc[mt][nt][0] + b0, y01 = acc[mt][nt][1] + b1;
            float y10 = acc[mt][nt][2] + b0, y11 = acc[mt][nt][3] + b1;
            if (v0) *(float2*)(C + (size_t)r0 * DIM + n) = make_float2(y00, y01);
            if (v1) *(float2*)(C + (size_t)(r0 + 8) * DIM + n) = make_float2(y10, y11);
            if (v0) { s_loc[nt][0] += y00; s_loc[nt][1] += y01;
                      q_loc[nt][0] += y00 * y00; q_loc[nt][1] += y01 * y01; }
            if (v1) { s_loc[nt][0] += y10; s_loc[nt][1] += y11;
                      q_loc[nt][0] += y10 * y10; q_loc[nt][1] += y11 * y11; }
        }
    }
    __syncthreads();
    float* sS = (float*)smem;
    float* sQ = sS + 128;
    if (tid < 128) { sS[tid] = 0.f; sQ[tid] = 0.f; }
    __syncthreads();
#pragma unroll
    for (int nt = 0; nt < 4; nt++) {
        int n = warpN * 32 + nt * 8 + 2 * tg;
        atomicAdd(&sS[n], s_loc[nt][0]);
        atomicAdd(&sS[n + 1], s_loc[nt][1]);
        atomicAdd(&sQ[n], q_loc[nt][0]);
        atomicAdd(&sQ[n + 1], q_loc[nt][1]);
    }
    __syncthreads();
    if (tid < 128) {
        atomicAdd(&g_tsum[bz * DIM + tid], (double)sS[tid]);
        atomicAdd(&g_tsumsq[bz * DIM + tid], (double)sQ[tid]);
    }
}

// =================== fused node chain: h2 -> node_emb -> srcterm ============
// Row-local chain kept in SMEM as split-bf16 fragments between stages.
__global__ void __launch_bounds__(256, 1)
k_nfused(const float* __restrict__ l1b, const float* __restrict__ l2b,
         const __nv_bfloat16* __restrict__ Wch, const __nv_bfloat16* __restrict__ Wcl,
         const __nv_bfloat16* __restrict__ l2h, const __nv_bfloat16* __restrict__ l2l,
         const __nv_bfloat16* __restrict__ psh, const __nv_bfloat16* __restrict__ psl,
         float* __restrict__ out) {
    extern __shared__ char smem[];
    uint32_t sbase = (uint32_t)__cvta_generic_to_shared(smem);
    uint32_t* wA0h = (uint32_t*)smem;
    uint32_t* wA0l = wA0h + TILEB / 4;
    uint32_t* wA1h = wA0h + 2 * (TILEB / 4);
    uint32_t* wA1l = wA0h + 3 * (TILEB / 4);
    uint32_t* wBh  = wA0h + 4 * (TILEB / 4);
    uint32_t* wBl  = wA0h + 5 * (TILEB / 4);
    int tid = threadIdx.x, wid = tid >> 5, lane = tid & 31;
    int g = lane >> 2, tg = lane & 3;
    int warpM = wid & 1, warpN = wid >> 1;
    int row0 = blockIdx.x * 128;

    uint32_t aoff = a_ldsm_off(lane, warpM);
    uint32_t boff = b_ldsm_off(lane, warpN);
    uint32_t A0H = sbase + aoff,             A0L = sbase + TILEB + aoff;
    uint32_t A1H = sbase + 2 * TILEB + aoff, A1L = sbase + 3 * TILEB + aoff;
    uint32_t BH  = sbase + 4 * TILEB + boff, BL  = sbase + 5 * TILEB + boff;

    float acc[4][4][4];
#pragma unroll
    for (int mt = 0; mt < 4; mt++)
#pragma unroll
        for (int nt = 0; nt < 4; nt++)
#pragma unroll
            for (int j = 0; j < 4; j++) acc[mt][nt][j] = 0.f;

    // ---- stage 1: h2 = relu(Z @ Wc + l1b); Z = relu(ta*T + tc); K=384 ----
    for (int kk = 0; kk < 384; kk += 64) {
#pragma unroll
        for (int it = 0; it < 8; it++) {
            int idx = tid + it * 256;
            int r = idx >> 4, cq = idx & 15;
            int k = kk + cq * 4;
            int grow = row0 + r;
            float4 a = make_float4(0.f, 0.f, 0.f, 0.f);
            if (grow < NSRC) {
                int blk = k >> 7;
                float4 t = *(const float4*)(g_T + ((size_t)(blk * NSRC + grow)) * DIM + (k & 127));
                float4 ta = *(const float4*)(g_ta + k);
                float4 tc = *(const float4*)(g_tc + k);
                a.x = fmaxf(ta.x * t.x + tc.x, 0.f);
                a.y = fmaxf(ta.y * t.y + tc.y, 0.f);
                a.z = fmaxf(ta.z * t.z + tc.z, 0.f);
                a.w = fmaxf(ta.w * t.w + tc.w, 0.f);
            }
            store_split(wA0h, wA0l, r * LDW + cq * 2, a);
        }
#pragma unroll
        for (int it = 0; it < 4; it++) {
            int idx = tid + it * 256;
            int n = idx >> 3, j = idx & 7;
            *(uint4*)(wBh + n * LDW + j * 4) =
                *(const uint4*)((const char*)Wch + ((size_t)n * 384 + kk + j * 8) * 2);
            *(uint4*)(wBl + n * LDW + j * 4) =
                *(const uint4*)((const char*)Wcl + ((size_t)n * 384 + kk + j * 8) * 2);
        }
        __syncthreads();
        mma_chunk(A0H, A0L, BH, BL, acc, 4);
        __syncthreads();
    }
    // epilogue 1: h2 fragments -> A buffers (split-bf16), relu + bias
#pragma unroll
    for (int mt = 0; mt < 4; mt++) {
        int rr0 = warpM * 64 + mt * 16 + g;
#pragma unroll
        for (int nt = 0; nt < 4; nt++) {
            int col = warpN * 32 + nt * 8 + 2 * tg;
            float b0 = l1b[col], b1 = l1b[col + 1];
            float y00 = fmaxf(acc[mt][nt][0] + b0, 0.f);
            float y01 = fmaxf(acc[mt][nt][1] + b1, 0.f);
            float y10 = fmaxf(acc[mt][nt][2] + b0, 0.f);
            float y11 = fmaxf(acc[mt][nt][3] + b1, 0.f);
            uint32_t* dh = (col < 64) ? wA0h : wA1h;
            uint32_t* dl = (col < 64) ? wA0l : wA1l;
            int wofs = (col & 63) >> 1;
            uint32_t h, l;
            split_pair(y00, y01, h, l);
            dh[rr0 * LDW + wofs] = h; dl[rr0 * LDW + wofs] = l;
            split_pair(y10, y11, h, l);
            dh[(rr0 + 8) * LDW + wofs] = h; dl[(rr0 + 8) * LDW + wofs] = l;
        }
    }
    __syncthreads();

    // ---- stage 2: node_emb = h2 @ l2 + l2b (K=128, 2 chunks) ----
#pragma unroll
    for (int mt = 0; mt < 4; mt++)
#pragma unroll
        for (int nt = 0; nt < 4; nt++)
#pragma unroll
            for (int j = 0; j < 4; j++) acc[mt][nt][j] = 0.f;
    for (int c = 0; c < 2; c++) {
#pragma unroll
        for (int it = 0; it < 4; it++) {
            int idx = tid + it * 256;
            int n = idx >> 3, j = idx & 7;
            *(uint4*)(wBh + n * LDW + j * 4) =
                *(const uint4*)((const char*)l2h + ((size_t)n * 128 + c * 64 + j * 8) * 2);
            *(uint4*)(wBl + n * LDW + j * 4) =
                *(const uint4*)((const char*)l2l + ((size_t)n * 128 + c * 64 + j * 8) * 2);
        }
        __syncthreads();
        mma_chunk(c ? A1H : A0H, c ? A1L : A0L, BH, BL, acc, 4);
        __syncthreads();
    }
    // epilogue 2: write node_emb to out, convert into A buffers for stage 3
#pragma unroll
    for (int mt = 0; mt < 4; mt++) {
        int rr0 = warpM * 64 + mt * 16 + g;
        int gr0 = row0 + rr0;
#pragma unroll
        for (int nt = 0; nt < 4; nt++) {
            int col = warpN * 32 + nt * 8 + 2 * tg;
            float b0 = l2b[col], b1 = l2b[col + 1];
            float y00 = acc[mt][nt][0] + b0, y01 = acc[mt][nt][1] + b1;
            float y10 = acc[mt][nt][2] + b0, y11 = acc[mt][nt][3] + b1;
            if (gr0 < NSRC)
                *(float2*)(out + (size_t)gr0 * DIM + col) = make_float2(y00, y01);
            if (gr0 + 8 < NSRC)
                *(float2*)(out + (size_t)(gr0 + 8) * DIM + col) = make_float2(y10, y11);
            uint32_t* dh = (col < 64) ? wA0h : wA1h;
            uint32_t* dl = (col < 64) ? wA0l : wA1l;
            int wofs = (col & 63) >> 1;
            uint32_t h, l;
            split_pair(y00, y01, h, l);
            dh[rr0 * LDW + wofs] = h; dl[rr0 * LDW + wofs] = l;
            split_pair(y10, y11, h, l);
            dh[(rr0 + 8) * LDW + wofs] = h; dl[(rr0 + 8) * LDW + wofs] = l;
        }
    }
    __syncthreads();

    // ---- stage 3: srcterm = node_emb @ ps + combB (K=128, 2 chunks) ----
#pragma unroll
    for (int mt = 0; mt < 4; mt++)
#pragma unroll
        for (int nt = 0; nt < 4; nt++)
#pragma unroll
            for (int j = 0; j < 4; j++) acc[mt][nt][j] = 0.f;
    for (int c = 0; c < 2; c++) {
#pragma unroll
        for (int it = 0; it < 4; it++) {
            int idx = tid + it * 256;
            int n = idx >> 3, j = idx & 7;
            *(uint4*)(wBh + n * LDW + j * 4) =
                *(const uint4*)((const char*)psh + ((size_t)n * 128 + c * 64 + j * 8) * 2);
            *(uint4*)(wBl + n * LDW + j * 4) =
                *(const uint4*)((const char*)psl + ((size_t)n * 128 + c * 64 + j * 8) * 2);
        }
        __syncthreads();
        mma_chunk(c ? A1H : A0H, c ? A1L : A0L, BH, BL, acc, 4);
        __syncthreads();
    }
#pragma unroll
    for (int mt = 0; mt < 4; mt++) {
        int gr0 = row0 + warpM * 64 + mt * 16 + g;
#pragma unroll
        for (int nt = 0; nt < 4; nt++) {
            int col = warpN * 32 + nt * 8 + 2 * tg;
            float b0 = g_combB[col], b1 = g_combB[col + 1];
            if (gr0 < NSRC)
                *(float2*)(g_srcterm + (size_t)gr0 * DIM + col) =
                    make_float2(acc[mt][nt][0] + b0, acc[mt][nt][1] + b1);
            if (gr0 + 8 < NSRC)
                *(float2*)(g_srcterm + (size_t)(gr0 + 8) * DIM + col) =
                    make_float2(acc[mt][nt][2] + b0, acc[mt][nt][3] + b1);
        }
    }
}

// ---------------- BN coefficient finalization -------------------------------
__global__ void k_coef1(const float* __restrict__ bng, const float* __restrict__ bnb,
                        const float* __restrict__ psb, const float* __restrict__ ptb) {
    int t = blockIdx.x * blockDim.x + threadIdx.x;
    if (t < 3 * DIM) {
        double mean = g_tsum[t] / NSRC;
        double var = g_tsumsq[t] / NSRC - mean * mean;
        float a = bng[t] * rsqrtf((float)var + BN_EPS);
        g_ta[t] = a;
        g_tc[t] = bnb[t] - a * (float)mean;
    }
    if (t < DIM) g_combB[t] = psb[t] + ptb[t];
}

__global__ void k_coef2(const float* __restrict__ peg, const float* __restrict__ peb) {
    int t = threadIdx.x;
    double s = 0.0, q = 0.0;
#pragma unroll
    for (int b2 = 0; b2 < 32; b2++) {
        s += g_psumB[b2 * DIM + t];
        q += g_psumsqB[b2 * DIM + t];
    }
    double mean = s / NEDGE;
    double var = q / NEDGE - mean * mean;
    float a = peg[t] * rsqrtf((float)var + BN_EPS);
    g_peA[t] = a;
    g_peC[t] = peb[t] - a * (float)mean;
}

// ---------------- scores (y already includes srcterm) ------------------------
__global__ void k_scores(const float* __restrict__ sw) {
    int w = (blockIdx.x * blockDim.x + threadIdx.x) >> 5;
    int lane = threadIdx.x & 31;
    int e0 = w * 64;
    float a[4], c4[4], wv[4];
#pragma unroll
    for (int j = 0; j < 4; j++) {
        int cc = lane + 32 * j;
        a[j] = g_peA[cc]; c4[j] = g_peC[cc]; wv[j] = sw[cc];
    }
    for (int e = e0; e < e0 + 64; e++) {
        const float* yr = g_xg + (size_t)e * DIM;
        float p = 0.f;
#pragma unroll
        for (int j = 0; j < 4; j++) {
            float v = a[j] * yr[lane + 32 * j] + c4[j];
            v = (v > 0.f) ? v : 0.f;
            p += v * wv[j];
        }
#pragma unroll
        for (int o = 16; o; o >>= 1) p += __shfl_xor_sync(0xffffffffu, p, o);
        if (lane == 0) g_scores[e] = p;
    }
}

// ---------------- top-k ------------------------------------------------------
__device__ __forceinline__ bool kbetter(float s1, int i1, float s2, int i2) {
    return (s1 > s2) || (s1 == s2 && i1 < i2);
}
__device__ __forceinline__ void top_insert(float* bs, int* bi, float v, int e) {
    if (!kbetter(v, e, bs[TOPN - 1], bi[TOPN - 1])) return;
    int p = TOPN - 1;
    while (p > 0 && kbetter(v, e, bs[p - 1], bi[p - 1])) {
        bs[p] = bs[p - 1]; bi[p] = bi[p - 1]; p--;
    }
    bs[p] = v; bi[p] = e;
}

__global__ void k_top_a() {
    float bs[TOPN]; int bi[TOPN];
#pragma unroll
    for (int j = 0; j < TOPN; j++) { bs[j] = -1e30f; bi[j] = 0x7fffffff; }
    int t = blockIdx.x * 256 + threadIdx.x;
    for (int e = t; e < NEDGE; e += 128 * 256) {
        top_insert(bs, bi, g_scores[e], e);
    }
    __shared__ float ss[256 * TOPN];
    __shared__ int si[256 * TOPN];
#pragma unroll
    for (int j = 0; j < TOPN; j++) {
        ss[threadIdx.x * TOPN + j] = bs[j];
        si[threadIdx.x * TOPN + j] = bi[j];
    }
    __syncthreads();
    if (threadIdx.x == 0) {
        float cs[TOPN]; int ci[TOPN];
#pragma unroll
        for (int j = 0; j < TOPN; j++) { cs[j] = -1e30f; ci[j] = 0x7fffffff; }
        for (int k = 0; k < 256 * TOPN; k++) top_insert(cs, ci, ss[k], si[k]);
        for (int j = 0; j < TOPN; j++) {
            g_cs[blockIdx.x * TOPN + j] = cs[j];
            g_ci[blockIdx.x * TOPN + j] = ci[j];
        }
    }
}

__global__ void k_top_b(float* __restrict__ out) {
    if (threadIdx.x == 0) {
        float cs[TOPN]; int ci[TOPN];
#pragma unroll
        for (int j = 0; j < TOPN; j++) { cs[j] = -1e30f; ci[j] = 0x7fffffff; }
        for (int k = 0; k < 128 * TOPN; k++) top_insert(cs, ci, g_cs[k], g_ci[k]);
        for (int j = 0; j < TOPN; j++) {
            out[(size_t)NSRC * DIM + j] = cs[j];
            out[(size_t)NSRC * DIM + TOPN + j] = (float)ci[j];
        }
    }
}

// ---------------- host entry -------------------------------------------------
extern "C" void kernel_launch(void* const* d_in, const int* in_sizes, int n_in,
                              void* d_out, int out_size) {
    bool dictorder = (in_sizes[2] == NEDGE);
    const float* paths = (const float*)d_in[0];
    const float* pf    = (const float*)d_in[1];
    const int*   sid   = (const int*)d_in[dictorder ? 2 : 19];
    int b = dictorder ? 3 : 2;
    const float* cew = (const float*)d_in[b + 0];
    const float* ceb = (const float*)d_in[b + 1];
    const float* w1  = (const float*)d_in[b + 2];
    const float* bng = (const float*)d_in[b + 3];
    const float* bnb = (const float*)d_in[b + 4];
    const float* w2  = (const float*)d_in[b + 5];
    const float* l1W = (const float*)d_in[b + 6];
    const float* l1b = (const float*)d_in[b + 7];
    const float* l2W = (const float*)d_in[b + 8];
    const float* l2b = (const float*)d_in[b + 9];
    const float* psW = (const float*)d_in[b + 10];
    const float* psb = (const float*)d_in[b + 11];
    const float* ptW = (const float*)d_in[b + 12];
    const float* ptb = (const float*)d_in[b + 13];
    const float* peg = (const float*)d_in[b + 14];
    const float* peb = (const float*)d_in[b + 15];
    const float* sw  = (const float*)d_in[b + 16];
    float* out = (float*)d_out;

    void *p_agg, *p_Wc, *p_Wei1, *p_T, *p_cvec;
    void *p_Wbh, *p_Wbl, *p_Wch, *p_Wcl, *p_l2h, *p_l2l, *p_psh, *p_psl;
    cudaGetSymbolAddress(&p_agg, g_agg);
    cudaGetSymbolAddress(&p_Wc, g_Wc);
    cudaGetSymbolAddress(&p_Wei1, g_Wei1);
    cudaGetSymbolAddress(&p_T, g_T);
    cudaGetSymbolAddress(&p_cvec, g_cvec);
    cudaGetSymbolAddress(&p_Wbh, g_Wbh);
    cudaGetSymbolAddress(&p_Wbl, g_Wbl);
    cudaGetSymbolAddress(&p_Wch, g_Wch);
    cudaGetSymbolAddress(&p_Wcl, g_Wcl);
    cudaGetSymbolAddress(&p_l2h, g_l2h);
    cudaGetSymbolAddress(&p_l2l, g_l2l);
    cudaGetSymbolAddress(&p_psh, g_psh);
    cudaGetSymbolAddress(&p_psl, g_psl);
    const __nv_bfloat16* Wbh = (const __nv_bfloat16*)p_Wbh;
    const __nv_bfloat16* Wbl = (const __nv_bfloat16*)p_Wbl;
    const __nv_bfloat16* Wch = (const __nv_bfloat16*)p_Wch;
    const __nv_bfloat16* Wcl = (const __nv_bfloat16*)p_Wcl;
    const __nv_bfloat16* l2h = (const __nv_bfloat16*)p_l2h;
    const __nv_bfloat16* l2l = (const __nv_bfloat16*)p_l2l;
    const __nv_bfloat16* psh = (const __nv_bfloat16*)p_psh;
    const __nv_bfloat16* psl = (const __nv_bfloat16*)p_psl;

    cudaFuncSetAttribute(k_edge_gemm, cudaFuncAttributeMaxDynamicSharedMemorySize, EG_SMEM);
    cudaFuncSetAttribute(k_ncat, cudaFuncAttributeMaxDynamicSharedMemorySize, EG_SMEM);
    cudaFuncSetAttribute(k_nfused, cudaFuncAttributeMaxDynamicSharedMemorySize, NF_SMEM);

    const int NODE_BLKS = (NSRC + 127) / 128;   // 79

    k_reset<<<40, 256>>>();
    k_hist<<<(NEDGE + 255) / 256, 256>>>(sid);
    k_scan<<<1, 1024>>>();
    k_scatter<<<(NEDGE + 255) / 256, 256>>>(sid);
    k_prepB<<<128, 256>>>(ptW);
    k_agg<<<(NSRC * 32 + 255) / 256, 256>>>(pf);

    gemm128<<<dim3(1, 3), 256>>>(w2, DIM, DIM, DIM, (long)DIM * DIM,
                                 l1W, (long)DIM * DIM, (float*)p_Wc, (long)DIM * DIM);
    gemm128<<<dim3(2, 3), 256>>>(cew, EDIM, DIM, DIM, (long)EDIM * DIM,
                                 w1, (long)DIM * DIM, (float*)p_Wei1, (long)EDIM * DIM);
    k_cvec<<<3, 128>>>(ceb, w1);

    k_prepWbig<<<dim3(192, 3), 256>>>(w1);
    k_prepWgen<<<192, 256>>>((const float*)p_Wc, (__nv_bfloat16*)p_Wch,
                             (__nv_bfloat16*)p_Wcl, 384, 384);
    k_prepWgen<<<64, 256>>>(l2W, (__nv_bfloat16*)p_l2h, (__nv_bfloat16*)p_l2l, 128, 128);
    k_prepWgen<<<64, 256>>>(psW, (__nv_bfloat16*)p_psh, (__nv_bfloat16*)p_psl, 128, 128);

    // T_cat = [agg|paths] @ Wbig_i + c_i  (+ BN stats)
    k_ncat<<<dim3(NODE_BLKS, 3), 256, EG_SMEM>>>(
        (const float*)p_agg, paths, Wbh, Wbl, (const float*)p_cvec, (float*)p_T);
    k_coef1<<<2, 256>>>(bng, bnb, psb, ptb);

    // fused: h2 -> node_emb(out) -> srcterm, one launch
    k_nfused<<<NODE_BLKS, 256, NF_SMEM>>>(l1b, l2b, Wch, Wcl, l2h, l2l, psh, psl, out);

    // edge GEMM (HMMA split-bf16, ldmatrix) with fused srcterm add + BN stats
    k_edge_gemm<<<NEDGE / 128, 256, EG_SMEM>>>(pf, sid);

    k_coef2<<<1, 128>>>(peg, peb);
    k_scores<<<NEDGE / 512, 256>>>(sw);
    k_top_a<<<128, 256>>>();
    k_top_b<<<1, 32>>>(out);
}

// round 16
// speedup vs baseline: 1.0952x; 1.0599x over previous
#include <cuda_runtime.h>
#include <cuda_bf16.h>
#include <cuda_fp16.h>
#include <math.h>
#include <stdint.h>

#define NSRC 10000
#define NEDGE 320000
#define DIM 128
#define EDIM 236
#define TOPN 6
#define BN_EPS 1e-5f

// ---------------- scratch (device globals; no allocation allowed) ----------
__device__ float  g_agg[(size_t)NSRC * EDIM];
__device__ float  g_xg[(size_t)NEDGE * DIM];         // holds y = xg + srcterm[sid]
__device__ float  g_srcterm[(size_t)NSRC * DIM];
__device__ float  g_T[(size_t)3 * NSRC * DIM];
__device__ float  g_Wc[3 * DIM * DIM];
__device__ float  g_Wei1[3 * EDIM * DIM];
__device__ float  g_cvec[3 * DIM];
__device__ float  g_scores[NEDGE];
__device__ int    g_cnt[NSRC];
__device__ int    g_off[NSRC + 1];
__device__ int    g_cur[NSRC];
__device__ int    g_order[NEDGE];
__device__ double g_tsum[3 * DIM], g_tsumsq[3 * DIM];
__device__ double g_psumB[32 * DIM], g_psumsqB[32 * DIM];
__device__ float  g_ta[3 * DIM], g_tc[3 * DIM];
__device__ float  g_peA[DIM], g_peC[DIM];
__device__ float  g_combB[DIM];
__device__ float  g_cs[128 * TOPN];
__device__ int    g_ci[128 * TOPN];
// pre-converted weights
__device__ __half        g_Bf[128 * 256];                       // pe_tgt_W fp16, n-major
__device__ __nv_bfloat16 g_Wbh[3 * 128 * 384], g_Wbl[3 * 128 * 384]; // Wbig split-bf16
__device__ __nv_bfloat16 g_Wch[128 * 384], g_Wcl[128 * 384];
__device__ __nv_bfloat16 g_l2h[128 * 128], g_l2l[128 * 128];
__device__ __nv_bfloat16 g_psh[128 * 128], g_psl[128 * 128];

// ---------------- small utility kernels ------------------------------------
__global__ void k_reset() {
    int t = blockIdx.x * blockDim.x + threadIdx.x;
    if (t < NSRC) g_cnt[t] = 0;
    if (t < 3 * DIM) { g_tsum[t] = 0.0; g_tsumsq[t] = 0.0; }
    if (t < 32 * DIM) { g_psumB[t] = 0.0; g_psumsqB[t] = 0.0; }
}

__global__ void k_hist(const int* __restrict__ sid) {
    int e = blockIdx.x * blockDim.x + threadIdx.x;
    if (e < NEDGE) atomicAdd(&g_cnt[sid[e]], 1);
}

__global__ void k_scan() {
    __shared__ int s[1024];
    int t = threadIdx.x;
    int base = t * 10;
    int loc[10];
    int acc = 0;
#pragma unroll
    for (int j = 0; j < 10; j++) {
        int idx = base + j;
        int v = (idx < NSRC) ? g_cnt[idx] : 0;
        loc[j] = acc; acc += v;
    }
    s[t] = acc;
    __syncthreads();
    for (int off = 1; off < 1024; off <<= 1) {
        int v = (t >= off) ? s[t - off] : 0;
        __syncthreads();
        s[t] += v;
        __syncthreads();
    }
    int pre = (t > 0) ? s[t - 1] : 0;
#pragma unroll
    for (int j = 0; j < 10; j++) {
        int idx = base + j;
        if (idx < NSRC) { g_off[idx] = pre + loc[j]; g_cur[idx] = pre + loc[j]; }
    }
    if (t == 0) g_off[NSRC] = NEDGE;
}

__global__ void k_scatter(const int* __restrict__ sid) {
    int e = blockIdx.x * blockDim.x + threadIdx.x;
    if (e < NEDGE) {
        int p = atomicAdd(&g_cur[sid[e]], 1);
        g_order[p] = e;
    }
}

__device__ __forceinline__ void splitbf(float v, __nv_bfloat16& h, __nv_bfloat16& l) {
    h = __float2bfloat16(v);
    l = __float2bfloat16(v - __bfloat162float(h));
}

// edge-B prep: pe_tgt_W[236,128] -> fp16, n-major [n][256]
__global__ void k_prepB(const float* __restrict__ ptW) {
    int idx = blockIdx.x * 256 + threadIdx.x;
    if (idx >= 128 * 256) return;
    int k = idx >> 7, n = idx & 127;
    float b = (k < EDIM) ? ptW[(size_t)k * DIM + n] : 0.f;
    g_Bf[n * 256 + k] = __float2half_rn(b);
}

__global__ void k_prepWbig(const float* __restrict__ w1) {
    int i = blockIdx.y;
    int idx = blockIdx.x * 256 + threadIdx.x;
    int n = idx / 384, k = idx % 384;
    float v = 0.f;
    if (k < EDIM) v = g_Wei1[i * EDIM * DIM + k * DIM + n];
    else if (k < EDIM + DIM) v = w1[i * DIM * DIM + (k - EDIM) * DIM + n];
    __nv_bfloat16 h, l; splitbf(v, h, l);
    g_Wbh[i * 128 * 384 + n * 384 + k] = h;
    g_Wbl[i * 128 * 384 + n * 384 + k] = l;
}

__global__ void k_prepWgen(const float* __restrict__ src, __nv_bfloat16* __restrict__ dh,
                           __nv_bfloat16* __restrict__ dl, int K, int Kpad) {
    int idx = blockIdx.x * 256 + threadIdx.x;
    if (idx >= 128 * Kpad) return;
    int n = idx / Kpad, k = idx % Kpad;
    float v = (k < K) ? src[(size_t)k * DIM + n] : 0.f;
    __nv_bfloat16 h, l; splitbf(v, h, l);
    dh[n * Kpad + k] = h;
    dl[n * Kpad + k] = l;
}

__global__ void k_cvec(const float* __restrict__ ceb, const float* __restrict__ w1) {
    int i = blockIdx.x, n = threadIdx.x;
    float s = 0.f;
    for (int k = 0; k < DIM; k++)
        s += ceb[i * DIM + k] * w1[i * DIM * DIM + k * DIM + n];
    g_cvec[i * DIM + n] = s;
}

__global__ void k_agg(const float* __restrict__ pf) {
    int w = (blockIdx.x * blockDim.x + threadIdx.x) >> 5;
    int lane = threadIdx.x & 31;
    if (w >= NSRC) return;
    float4 a0 = make_float4(0.f, 0.f, 0.f, 0.f);
    float4 a1 = make_float4(0.f, 0.f, 0.f, 0.f);
    int s = g_off[w], e2 = g_off[w + 1];
    for (int p = s; p < e2; p++) {
        const float4* r = (const float4*)(pf + (size_t)g_order[p] * EDIM);
        float4 v = __ldg(r + lane);
        a0.x += fmaxf(v.x, 0.f); a0.y += fmaxf(v.y, 0.f);
        a0.z += fmaxf(v.z, 0.f); a0.w += fmaxf(v.w, 0.f);
        if (lane < 27) {
            float4 v2 = __ldg(r + 32 + lane);
            a1.x += fmaxf(v2.x, 0.f); a1.y += fmaxf(v2.y, 0.f);
            a1.z += fmaxf(v2.z, 0.f); a1.w += fmaxf(v2.w, 0.f);
        }
    }
    float4* outp = (float4*)(g_agg + (size_t)w * EDIM);
    outp[lane] = a0;
    if (lane < 27) outp[32 + lane] = a1;
}

// ---------------- small fp32 GEMM (C = A@W), batched over blockIdx.y --------
__global__ void __launch_bounds__(256)
gemm128(const float* __restrict__ A, int M, int K, int lda, long astr,
        const float* __restrict__ W, long wstr,
        float* __restrict__ C, long cstr) {
    int bz = blockIdx.y;
    A += (size_t)bz * astr;
    W += (size_t)bz * wstr;
    C += (size_t)bz * cstr;

    __shared__ float sA[8][128];
    __shared__ float sW[8][128];
    int tid = threadIdx.x;
    int row0 = blockIdx.x * 128;
    int tx = tid & 15, ty = tid >> 4;
    float acc[8][8];
#pragma unroll
    for (int i = 0; i < 8; i++)
#pragma unroll
        for (int j = 0; j < 8; j++) acc[i][j] = 0.f;

    int ar = tid >> 1;
    int ac = (tid & 1) * 4;
    int wk = (tid * 4) >> 7;
    int wc = (tid * 4) & 127;

    for (int kk = 0; kk < K; kk += 8) {
        float4 av = make_float4(0.f, 0.f, 0.f, 0.f);
        int grow = row0 + ar;
        if (grow < M) {
            int k = kk + ac;
            if (k + 3 < K) {
                av = *(const float4*)(A + (size_t)grow * lda + k);
            } else {
#pragma unroll
                for (int j = 0; j < 4; j++) {
                    int kj = k + j;
                    ((float*)&av)[j] = (kj < K) ? A[(size_t)grow * lda + kj] : 0.f;
                }
            }
        }
        sA[ac + 0][ar] = av.x; sA[ac + 1][ar] = av.y;
        sA[ac + 2][ar] = av.z; sA[ac + 3][ar] = av.w;

        float4 wv = make_float4(0.f, 0.f, 0.f, 0.f);
        if (kk + wk < K) wv = *(const float4*)(W + (size_t)(kk + wk) * 128 + wc);
        *(float4*)&sW[wk][wc] = wv;
        __syncthreads();

#pragma unroll
        for (int k = 0; k < 8; k++) {
            float4 a0 = *(float4*)&sA[k][ty * 8];
            float4 a1 = *(float4*)&sA[k][ty * 8 + 4];
            float4 b0 = *(float4*)&sW[k][tx * 8];
            float4 b1 = *(float4*)&sW[k][tx * 8 + 4];
            float ra[8] = {a0.x, a0.y, a0.z, a0.w, a1.x, a1.y, a1.z, a1.w};
            float rb[8] = {b0.x, b0.y, b0.z, b0.w, b1.x, b1.y, b1.z, b1.w};
#pragma unroll
            for (int i = 0; i < 8; i++)
#pragma unroll
                for (int j = 0; j < 8; j++) acc[i][j] += ra[i] * rb[j];
        }
        __syncthreads();
    }
#pragma unroll
    for (int i = 0; i < 8; i++) {
        int row = row0 + ty * 8 + i;
        if (row < M)
#pragma unroll
            for (int j = 0; j < 8; j++)
                C[(size_t)row * DIM + tx * 8 + j] = acc[i][j];
    }
}

// =================== shared MMA machinery ===================================
#define LDE 72
#define LDW 36
#define ROWB 144                       // bytes per smem row
#define TILEB (128 * ROWB)             // 18432 bytes
#define EG_SMEM (2 * TILEB)            // edge kernel: Af, Bf (fp16)
#define NC_SMEM (4 * TILEB)            // ncat kernel: Ah, Al, Bh, Bl
#define NF_SMEM (6 * TILEB)            // fused node kernel

__device__ __forceinline__ void mma_bf16(float* c, const uint32_t* a, const uint32_t* b) {
    asm volatile(
        "mma.sync.aligned.m16n8k16.row.col.f32.bf16.bf16.f32 "
        "{%0,%1,%2,%3}, {%4,%5,%6,%7}, {%8,%9}, {%0,%1,%2,%3};"
        : "+f"(c[0]), "+f"(c[1]), "+f"(c[2]), "+f"(c[3])
        : "r"(a[0]), "r"(a[1]), "r"(a[2]), "r"(a[3]), "r"(b[0]), "r"(b[1]));
}
__device__ __forceinline__ void mma_f16(float* c, const uint32_t* a, const uint32_t* b) {
    asm volatile(
        "mma.sync.aligned.m16n8k16.row.col.f32.f16.f16.f32 "
        "{%0,%1,%2,%3}, {%4,%5,%6,%7}, {%8,%9}, {%0,%1,%2,%3};"
        : "+f"(c[0]), "+f"(c[1]), "+f"(c[2]), "+f"(c[3])
        : "r"(a[0]), "r"(a[1]), "r"(a[2]), "r"(a[3]), "r"(b[0]), "r"(b[1]));
}
__device__ __forceinline__ void ldsm4(uint32_t* r, uint32_t a) {
    asm volatile("ldmatrix.sync.aligned.m8n8.x4.shared.b16 {%0,%1,%2,%3}, [%4];"
                 : "=r"(r[0]), "=r"(r[1]), "=r"(r[2]), "=r"(r[3]) : "r"(a));
}
__device__ __forceinline__ uint32_t packbf(float x, float y) {
    union { __nv_bfloat162 b; uint32_t u; } c;
    c.b = __float22bfloat162_rn(make_float2(x, y));
    return c.u;
}
__device__ __forceinline__ uint32_t packh(float x, float y) {
    union { __half2 h; uint32_t u; } c;
    c.h = __floats2half2_rn(x, y);
    return c.u;
}
__device__ __forceinline__ void split_pair(float y0, float y1, uint32_t& h, uint32_t& l) {
    h = packbf(y0, y1);
    float r0 = y0 - __bfloat162float(__ushort_as_bfloat16((uint16_t)h));
    float r1 = y1 - __bfloat162float(__ushort_as_bfloat16((uint16_t)(h >> 16)));
    l = packbf(r0, r1);
}

__device__ __forceinline__ uint32_t a_ldsm_off(int lane, int warpM) {
    int row = warpM * 64 + (lane & 7) + ((lane >> 3) & 1) * 8;
    return (uint32_t)row * ROWB + (uint32_t)((lane >> 4) & 1) * 16;
}
__device__ __forceinline__ uint32_t b_ldsm_off(int lane, int warpN) {
    int row = warpN * 32 + ((lane >> 4) & 1) * 8 + (lane & 7);
    return (uint32_t)row * ROWB + (uint32_t)((lane >> 3) & 1) * 16;
}

// 3-product bf16 chunk (node kernels)
__device__ __forceinline__ void mma_chunk(uint32_t aH, uint32_t aL,
                                          uint32_t bH, uint32_t bL,
                                          float acc[4][4][4], int ksmax) {
    for (int ks = 0; ks < ksmax; ks++) {
        uint32_t kb = (uint32_t)ks * 32;
        uint32_t bh[8], bl[8];
        ldsm4(&bh[0], bH + kb);
        ldsm4(&bh[4], bH + 16 * ROWB + kb);
        ldsm4(&bl[0], bL + kb);
        ldsm4(&bl[4], bL + 16 * ROWB + kb);
#pragma unroll
        for (int mt = 0; mt < 4; mt++) {
            uint32_t ah[4], al[4];
            ldsm4(ah, aH + (uint32_t)mt * 16 * ROWB + kb);
            ldsm4(al, aL + (uint32_t)mt * 16 * ROWB + kb);
#pragma unroll
            for (int nt = 0; nt < 4; nt++) {
                mma_bf16(acc[mt][nt], ah, &bh[nt * 2]);
                mma_bf16(acc[mt][nt], ah, &bl[nt * 2]);
                mma_bf16(acc[mt][nt], al, &bh[nt * 2]);
            }
        }
    }
}

// single-product fp16 chunk (edge kernel)
__device__ __forceinline__ void mma_chunk1(uint32_t aF, uint32_t bF,
                                           float acc[4][4][4], int ksmax) {
    for (int ks = 0; ks < ksmax; ks++) {
        uint32_t kb = (uint32_t)ks * 32;
        uint32_t bh[8];
        ldsm4(&bh[0], bF + kb);
        ldsm4(&bh[4], bF + 16 * ROWB + kb);
#pragma unroll
        for (int mt = 0; mt < 4; mt++) {
            uint32_t ah[4];
            ldsm4(ah, aF + (uint32_t)mt * 16 * ROWB + kb);
#pragma unroll
            for (int nt = 0; nt < 4; nt++)
                mma_f16(acc[mt][nt], ah, &bh[nt * 2]);
        }
    }
}

__device__ __forceinline__ void store_split(uint32_t* sAh, uint32_t* sAl, int w, float4 a) {
    uint32_t h01 = packbf(a.x, a.y), h23 = packbf(a.z, a.w);
    float fx = a.x - __bfloat162float(__ushort_as_bfloat16((uint16_t)h01));
    float fy = a.y - __bfloat162float(__ushort_as_bfloat16((uint16_t)(h01 >> 16)));
    uint32_t l01 = packbf(fx, fy);
    fx = a.z - __bfloat162float(__ushort_as_bfloat16((uint16_t)h23));
    fy = a.w - __bfloat162float(__ushort_as_bfloat16((uint16_t)(h23 >> 16)));
    uint32_t l23 = packbf(fx, fy);
    sAh[w] = h01; sAh[w + 1] = h23;
    sAl[w] = l01; sAl[w + 1] = l23;
}

// =================== edge GEMM (fp16 single-product) + fused epilogue =======
__global__ void __launch_bounds__(256, 2)
k_edge_gemm(const float* __restrict__ pf, const int* __restrict__ sid) {
    extern __shared__ char smem[];
    uint32_t sbase = (uint32_t)__cvta_generic_to_shared(smem);
    uint32_t* sAf = (uint32_t*)smem;
    uint32_t* sBf = sAf + 128 * LDW;
    int tid = threadIdx.x, wid = tid >> 5, lane = tid & 31;
    int g = lane >> 2, tg = lane & 3;
    int warpM = wid & 1, warpN = wid >> 1;
    int row0 = blockIdx.x * 128;

    uint32_t aF = sbase + a_ldsm_off(lane, warpM);
    uint32_t bF = sbase + TILEB + b_ldsm_off(lane, warpN);

    float acc[4][4][4];
#pragma unroll
    for (int mt = 0; mt < 4; mt++)
#pragma unroll
        for (int nt = 0; nt < 4; nt++)
#pragma unroll
            for (int j = 0; j < 4; j++) acc[mt][nt][j] = 0.f;

    for (int kk = 0; kk < 256; kk += 64) {
#pragma unroll
        for (int it = 0; it < 8; it++) {
            int idx = tid + it * 256;
            int r = idx >> 4, cq = idx & 15;
            int k = kk + cq * 4;
            float4 a = make_float4(0.f, 0.f, 0.f, 0.f);
            if (k + 3 < EDIM)
                a = *(const float4*)(pf + (size_t)(row0 + r) * EDIM + k);
            int w = r * LDW + cq * 2;
            sAf[w] = packh(a.x, a.y);
            sAf[w + 1] = packh(a.z, a.w);
        }
#pragma unroll
        for (int it = 0; it < 4; it++) {
            int idx = tid + it * 256;
            int n = idx >> 3, j = idx & 7;
            *(uint4*)(sBf + n * LDW + j * 4) =
                *(const uint4*)((const char*)g_Bf + ((size_t)n * 256 + kk + j * 8) * 2);
        }
        __syncthreads();
        int ksmax = (kk == 192) ? 3 : 4;   // k 240..255 is all zero padding
        mma_chunk1(aF, bF, acc, ksmax);
        __syncthreads();
    }

    // fused epilogue: y = acc + srcterm[sid[r]], store, BN stats
    float s_loc[4][2], q_loc[4][2];
#pragma unroll
    for (int nt = 0; nt < 4; nt++) {
        s_loc[nt][0] = s_loc[nt][1] = 0.f;
        q_loc[nt][0] = q_loc[nt][1] = 0.f;
    }
#pragma unroll
    for (int mt = 0; mt < 4; mt++) {
        int r0 = row0 + warpM * 64 + mt * 16 + g;
        const float* st0 = g_srcterm + (size_t)sid[r0] * DIM;
        const float* st1 = g_srcterm + (size_t)sid[r0 + 8] * DIM;
#pragma unroll
        for (int nt = 0; nt < 4; nt++) {
            int n = warpN * 32 + nt * 8 + 2 * tg;
            float2 e0 = *(const float2*)(st0 + n);
            float2 e1 = *(const float2*)(st1 + n);
            float y00 = acc[mt][nt][0] + e0.x, y01 = acc[mt][nt][1] + e0.y;
            float y10 = acc[mt][nt][2] + e1.x, y11 = acc[mt][nt][3] + e1.y;
            *(float2*)(g_xg + (size_t)r0 * DIM + n) = make_float2(y00, y01);
            *(float2*)(g_xg + (size_t)(r0 + 8) * DIM + n) = make_float2(y10, y11);
            s_loc[nt][0] += y00 + y10; s_loc[nt][1] += y01 + y11;
            q_loc[nt][0] += y00 * y00 + y10 * y10;
            q_loc[nt][1] += y01 * y01 + y11 * y11;
        }
    }
    __syncthreads();
    float* sS = (float*)smem;
    float* sQ = sS + 128;
    if (tid < 128) { sS[tid] = 0.f; sQ[tid] = 0.f; }
    __syncthreads();
#pragma unroll
    for (int nt = 0; nt < 4; nt++) {
        int n = warpN * 32 + nt * 8 + 2 * tg;
        atomicAdd(&sS[n], s_loc[nt][0]);
        atomicAdd(&sS[n + 1], s_loc[nt][1]);
        atomicAdd(&sQ[n], q_loc[nt][0]);
        atomicAdd(&sQ[n + 1], q_loc[nt][1]);
    }
    __syncthreads();
    if (tid < 128) {
        int bkt = (blockIdx.x & 31) * DIM + tid;
        atomicAdd(&g_psumB[bkt], (double)sS[tid]);
        atomicAdd(&g_psumsqB[bkt], (double)sQ[tid]);
    }
}

// =================== T_cat node GEMM (split-bf16, BN stats) =================
__global__ void __launch_bounds__(256, 2)
k_ncat(const float* __restrict__ A1, const float* __restrict__ A2,
       const __nv_bfloat16* __restrict__ Wh, const __nv_bfloat16* __restrict__ Wl,
       const float* __restrict__ bias, float* __restrict__ C) {
    int bz = blockIdx.y;
    Wh += (size_t)bz * 128 * 384; Wl += (size_t)bz * 128 * 384;
    bias += (size_t)bz * DIM; C += (size_t)bz * NSRC * DIM;

    extern __shared__ char smem[];
    uint32_t sbase = (uint32_t)__cvta_generic_to_shared(smem);
    uint32_t* sAh = (uint32_t*)smem;
    uint32_t* sAl = sAh + 128 * LDW;
    uint32_t* sBh = sAl + 128 * LDW;
    uint32_t* sBl = sBh + 128 * LDW;
    int tid = threadIdx.x, wid = tid >> 5, lane = tid & 31;
    int g = lane >> 2, tg = lane & 3;
    int warpM = wid & 1, warpN = wid >> 1;
    int row0 = blockIdx.x * 128;

    uint32_t aoff = a_ldsm_off(lane, warpM);
    uint32_t boff = b_ldsm_off(lane, warpN);
    uint32_t aH = sbase + aoff,            aL = sbase + TILEB + aoff;
    uint32_t bH = sbase + 2 * TILEB + boff, bL = sbase + 3 * TILEB + boff;

    float acc[4][4][4];
#pragma unroll
    for (int mt = 0; mt < 4; mt++)
#pragma unroll
        for (int nt = 0; nt < 4; nt++)
#pragma unroll
            for (int j = 0; j < 4; j++) acc[mt][nt][j] = 0.f;

    for (int kk = 0; kk < 384; kk += 64) {
#pragma unroll
        for (int it = 0; it < 8; it++) {
            int idx = tid + it * 256;
            int r = idx >> 4, cq = idx & 15;
            int k = kk + cq * 4;
            int grow = row0 + r;
            float4 a = make_float4(0.f, 0.f, 0.f, 0.f);
            if (grow < NSRC) {
                if (k < EDIM) a = *(const float4*)(A1 + (size_t)grow * EDIM + k);
                else if (k < EDIM + DIM) a = *(const float4*)(A2 + (size_t)grow * DIM + (k - EDIM));
            }
            store_split(sAh, sAl, r * LDW + cq * 2, a);
        }
#pragma unroll
        for (int it = 0; it < 4; it++) {
            int idx = tid + it * 256;
            int n = idx >> 3, j = idx & 7;
            const char* srch = (const char*)Wh + ((size_t)n * 384 + kk + j * 8) * 2;
            const char* srcl = (const char*)Wl + ((size_t)n * 384 + kk + j * 8) * 2;
            *(uint4*)(sBh + n * LDW + j * 4) = *(const uint4*)srch;
            *(uint4*)(sBl + n * LDW + j * 4) = *(const uint4*)srcl;
        }
        __syncthreads();
        int rem = (364 - kk + 15) >> 4;
        int ksmax = rem < 4 ? rem : 4;
        mma_chunk(aH, aL, bH, bL, acc, ksmax);
        __syncthreads();
    }

    float s_loc[4][2], q_loc[4][2];
#pragma unroll
    for (int nt = 0; nt < 4; nt++) {
        s_loc[nt][0] = s_loc[nt][1] = 0.f;
        q_loc[nt][0] = q_loc[nt][1] = 0.f;
    }
#pragma unroll
    for (int mt = 0; mt < 4; mt++) {
        int r0 = row0 + warpM * 64 + mt * 16 + g;
        bool v0 = r0 < NSRC, v1 = (r0 + 8) < NSRC;
#pragma unroll
        for (int nt = 0; nt < 4; nt++) {
            int n = warpN * 32 + nt * 8 + 2 * tg;
            float b0 = bias[n], b1 = bias[n + 1];
            float y00 = acc[mt][nt][0] + b0, y01 = acc[mt][nt][1] + b1;
            float y10 = acc[mt][nt][2] + b0, y11 = acc[mt][nt][3] + b1;
            if (v0) *(float2*)(C + (size_t)r0 * DIM + n) = make_float2(y00, y01);
            if (v1) *(float2*)(C + (size_t)(r0 + 8) * DIM + n) = make_float2(y10, y11);
            if (v0) { s_loc[nt][0] += y00; s_loc[nt][1] += y01;
                      q_loc[nt][0] += y00 * y00; q_loc[nt][1] += y01 * y01; }
            if (v1) { s_loc[nt][0] += y10; s_loc[nt][1] += y11;
                      q_loc[nt][0] += y10 * y10; q_loc[nt][1] += y11 * y11; }
        }
    }
    __syncthreads();
    float* sS = (float*)smem;
    float* sQ = sS + 128;
    if (tid < 128) { sS[tid] = 0.f; sQ[tid] = 0.f; }
    __syncthreads();
#pragma unroll
    for (int nt = 0; nt < 4; nt++) {
        int n = warpN * 32 + nt * 8 + 2 * tg;
        atomicAdd(&sS[n], s_loc[nt][0]);
        atomicAdd(&sS[n + 1], s_loc[nt][1]);
        atomicAdd(&sQ[n], q_loc[nt][0]);
        atomicAdd(&sQ[n + 1], q_loc[nt][1]);
    }
    __syncthreads();
    if (tid < 128) {
        atomicAdd(&g_tsum[bz * DIM + tid], (double)sS[tid]);
        atomicAdd(&g_tsumsq[bz * DIM + tid], (double)sQ[tid]);
    }
}

// =================== fused node chain: h2 -> node_emb -> srcterm ============
__global__ void __launch_bounds__(256, 1)
k_nfused(const float* __restrict__ l1b, const float* __restrict__ l2b,
         const __nv_bfloat16* __restrict__ Wch, const __nv_bfloat16* __restrict__ Wcl,
         const __nv_bfloat16* __restrict__ l2h, const __nv_bfloat16* __restrict__ l2l,
         const __nv_bfloat16* __restrict__ psh, const __nv_bfloat16* __restrict__ psl,
         float* __restrict__ out) {
    extern __shared__ char smem[];
    uint32_t sbase = (uint32_t)__cvta_generic_to_shared(smem);
    uint32_t* wA0h = (uint32_t*)smem;
    uint32_t* wA0l = wA0h + TILEB / 4;
    uint32_t* wA1h = wA0h + 2 * (TILEB / 4);
    uint32_t* wA1l = wA0h + 3 * (TILEB / 4);
    uint32_t* wBh  = wA0h + 4 * (TILEB / 4);
    uint32_t* wBl  = wA0h + 5 * (TILEB / 4);
    int tid = threadIdx.x, wid = tid >> 5, lane = tid & 31;
    int g = lane >> 2, tg = lane & 3;
    int warpM = wid & 1, warpN = wid >> 1;
    int row0 = blockIdx.x * 128;

    uint32_t aoff = a_ldsm_off(lane, warpM);
    uint32_t boff = b_ldsm_off(lane, warpN);
    uint32_t A0H = sbase + aoff,             A0L = sbase + TILEB + aoff;
    uint32_t A1H = sbase + 2 * TILEB + aoff, A1L = sbase + 3 * TILEB + aoff;
    uint32_t BH  = sbase + 4 * TILEB + boff, BL  = sbase + 5 * TILEB + boff;

    float acc[4][4][4];
#pragma unroll
    for (int mt = 0; mt < 4; mt++)
#pragma unroll
        for (int nt = 0; nt < 4; nt++)
#pragma unroll
            for (int j = 0; j < 4; j++) acc[mt][nt][j] = 0.f;

    // ---- stage 1: h2 = relu(Z @ Wc + l1b); Z = relu(ta*T + tc); K=384 ----
    for (int kk = 0; kk < 384; kk += 64) {
#pragma unroll
        for (int it = 0; it < 8; it++) {
            int idx = tid + it * 256;
            int r = idx >> 4, cq = idx & 15;
            int k = kk + cq * 4;
            int grow = row0 + r;
            float4 a = make_float4(0.f, 0.f, 0.f, 0.f);
            if (grow < NSRC) {
                int blk = k >> 7;
                float4 t = *(const float4*)(g_T + ((size_t)(blk * NSRC + grow)) * DIM + (k & 127));
                float4 ta = *(const float4*)(g_ta + k);
                float4 tc = *(const float4*)(g_tc + k);
                a.x = fmaxf(ta.x * t.x + tc.x, 0.f);
                a.y = fmaxf(ta.y * t.y + tc.y, 0.f);
                a.z = fmaxf(ta.z * t.z + tc.z, 0.f);
                a.w = fmaxf(ta.w * t.w + tc.w, 0.f);
            }
            store_split(wA0h, wA0l, r * LDW + cq * 2, a);
        }
#pragma unroll
        for (int it = 0; it < 4; it++) {
            int idx = tid + it * 256;
            int n = idx >> 3, j = idx & 7;
            *(uint4*)(wBh + n * LDW + j * 4) =
                *(const uint4*)((const char*)Wch + ((size_t)n * 384 + kk + j * 8) * 2);
            *(uint4*)(wBl + n * LDW + j * 4) =
                *(const uint4*)((const char*)Wcl + ((size_t)n * 384 + kk + j * 8) * 2);
        }
        __syncthreads();
        mma_chunk(A0H, A0L, BH, BL, acc, 4);
        __syncthreads();
    }
#pragma unroll
    for (int mt = 0; mt < 4; mt++) {
        int rr0 = warpM * 64 + mt * 16 + g;
#pragma unroll
        for (int nt = 0; nt < 4; nt++) {
            int col = warpN * 32 + nt * 8 + 2 * tg;
            float b0 = l1b[col], b1 = l1b[col + 1];
            float y00 = fmaxf(acc[mt][nt][0] + b0, 0.f);
            float y01 = fmaxf(acc[mt][nt][1] + b1, 0.f);
            float y10 = fmaxf(acc[mt][nt][2] + b0, 0.f);
            float y11 = fmaxf(acc[mt][nt][3] + b1, 0.f);
            uint32_t* dh = (col < 64) ? wA0h : wA1h;
            uint32_t* dl = (col < 64) ? wA0l : wA1l;
            int wofs = (col & 63) >> 1;
            uint32_t h, l;
            split_pair(y00, y01, h, l);
            dh[rr0 * LDW + wofs] = h; dl[rr0 * LDW + wofs] = l;
            split_pair(y10, y11, h, l);
            dh[(rr0 + 8) * LDW + wofs] = h; dl[(rr0 + 8) * LDW + wofs] = l;
        }
    }
    __syncthreads();

    // ---- stage 2: node_emb = h2 @ l2 + l2b (K=128, 2 chunks) ----
#pragma unroll
    for (int mt = 0; mt < 4; mt++)
#pragma unroll
        for (int nt = 0; nt < 4; nt++)
#pragma unroll
            for (int j = 0; j < 4; j++) acc[mt][nt][j] = 0.f;
    for (int c = 0; c < 2; c++) {
#pragma unroll
        for (int it = 0; it < 4; it++) {
            int idx = tid + it * 256;
            int n = idx >> 3, j = idx & 7;
            *(uint4*)(wBh + n * LDW + j * 4) =
                *(const uint4*)((const char*)l2h + ((size_t)n * 128 + c * 64 + j * 8) * 2);
            *(uint4*)(wBl + n * LDW + j * 4) =
                *(const uint4*)((const char*)l2l + ((size_t)n * 128 + c * 64 + j * 8) * 2);
        }
        __syncthreads();
        mma_chunk(c ? A1H : A0H, c ? A1L : A0L, BH, BL, acc, 4);
        __syncthreads();
    }
#pragma unroll
    for (int mt = 0; mt < 4; mt++) {
        int rr0 = warpM * 64 + mt * 16 + g;
        int gr0 = row0 + rr0;
#pragma unroll
        for (int nt = 0; nt < 4; nt++) {
            int col = warpN * 32 + nt * 8 + 2 * tg;
            float b0 = l2b[col], b1 = l2b[col + 1];
            float y00 = acc[mt][nt][0] + b0, y01 = acc[mt][nt][1] + b1;
            float y10 = acc[mt][nt][2] + b0, y11 = acc[mt][nt][3] + b1;
            if (gr0 < NSRC)
                *(float2*)(out + (size_t)gr0 * DIM + col) = make_float2(y00, y01);
            if (gr0 + 8 < NSRC)
                *(float2*)(out + (size_t)(gr0 + 8) * DIM + col) = make_float2(y10, y11);
            uint32_t* dh = (col < 64) ? wA0h : wA1h;
            uint32_t* dl = (col < 64) ? wA0l : wA1l;
            int wofs = (col & 63) >> 1;
            uint32_t h, l;
            split_pair(y00, y01, h, l);
            dh[rr0 * LDW + wofs] = h; dl[rr0 * LDW + wofs] = l;
            split_pair(y10, y11, h, l);
            dh[(rr0 + 8) * LDW + wofs] = h; dl[(rr0 + 8) * LDW + wofs] = l;
        }
    }
    __syncthreads();

    // ---- stage 3: srcterm = node_emb @ ps + combB (K=128, 2 chunks) ----
#pragma unroll
    for (int mt = 0; mt < 4; mt++)
#pragma unroll
        for (int nt = 0; nt < 4; nt++)
#pragma unroll
            for (int j = 0; j < 4; j++) acc[mt][nt][j] = 0.f;
    for (int c = 0; c < 2; c++) {
#pragma unroll
        for (int it = 0; it < 4; it++) {
            int idx = tid + it * 256;
            int n = idx >> 3, j = idx & 7;
            *(uint4*)(wBh + n * LDW + j * 4) =
                *(const uint4*)((const char*)psh + ((size_t)n * 128 + c * 64 + j * 8) * 2);
            *(uint4*)(wBl + n * LDW + j * 4) =
                *(const uint4*)((const char*)psl + ((size_t)n * 128 + c * 64 + j * 8) * 2);
        }
        __syncthreads();
        mma_chunk(c ? A1H : A0H, c ? A1L : A0L, BH, BL, acc, 4);
        __syncthreads();
    }
#pragma unroll
    for (int mt = 0; mt < 4; mt++) {
        int gr0 = row0 + warpM * 64 + mt * 16 + g;
#pragma unroll
        for (int nt = 0; nt < 4; nt++) {
            int col = warpN * 32 + nt * 8 + 2 * tg;
            float b0 = g_combB[col], b1 = g_combB[col + 1];
            if (gr0 < NSRC)
                *(float2*)(g_srcterm + (size_t)gr0 * DIM + col) =
                    make_float2(acc[mt][nt][0] + b0, acc[mt][nt][1] + b1);
            if (gr0 + 8 < NSRC)
                *(float2*)(g_srcterm + (size_t)(gr0 + 8) * DIM + col) =
                    make_float2(acc[mt][nt][2] + b0, acc[mt][nt][3] + b1);
        }
    }
}

// ---------------- BN coefficient finalization -------------------------------
__global__ void k_coef1(const float* __restrict__ bng, const float* __restrict__ bnb,
                        const float* __restrict__ psb, const float* __restrict__ ptb) {
    int t = blockIdx.x * blockDim.x + threadIdx.x;
    if (t < 3 * DIM) {
        double mean = g_tsum[t] / NSRC;
        double var = g_tsumsq[t] / NSRC - mean * mean;
        float a = bng[t] * rsqrtf((float)var + BN_EPS);
        g_ta[t] = a;
        g_tc[t] = bnb[t] - a * (float)mean;
    }
    if (t < DIM) g_combB[t] = psb[t] + ptb[t];
}

__global__ void k_coef2(const float* __restrict__ peg, const float* __restrict__ peb) {
    int t = threadIdx.x;
    double s = 0.0, q = 0.0;
#pragma unroll
    for (int b2 = 0; b2 < 32; b2++) {
        s += g_psumB[b2 * DIM + t];
        q += g_psumsqB[b2 * DIM + t];
    }
    double mean = s / NEDGE;
    double var = q / NEDGE - mean * mean;
    float a = peg[t] * rsqrtf((float)var + BN_EPS);
    g_peA[t] = a;
    g_peC[t] = peb[t] - a * (float)mean;
}

// ---------------- scores (y already includes srcterm) ------------------------
__global__ void k_scores(const float* __restrict__ sw) {
    int w = (blockIdx.x * blockDim.x + threadIdx.x) >> 5;
    int lane = threadIdx.x & 31;
    int e0 = w * 64;
    float a[4], c4[4], wv[4];
#pragma unroll
    for (int j = 0; j < 4; j++) {
        int cc = lane + 32 * j;
        a[j] = g_peA[cc]; c4[j] = g_peC[cc]; wv[j] = sw[cc];
    }
    for (int e = e0; e < e0 + 64; e++) {
        const float* yr = g_xg + (size_t)e * DIM;
        float p = 0.f;
#pragma unroll
        for (int j = 0; j < 4; j++) {
            float v = a[j] * yr[lane + 32 * j] + c4[j];
            v = (v > 0.f) ? v : 0.f;
            p += v * wv[j];
        }
#pragma unroll
        for (int o = 16; o; o >>= 1) p += __shfl_xor_sync(0xffffffffu, p, o);
        if (lane == 0) g_scores[e] = p;
    }
}

// ---------------- top-k ------------------------------------------------------
__device__ __forceinline__ bool kbetter(float s1, int i1, float s2, int i2) {
    return (s1 > s2) || (s1 == s2 && i1 < i2);
}
__device__ __forceinline__ void top_insert(float* bs, int* bi, float v, int e) {
    if (!kbetter(v, e, bs[TOPN - 1], bi[TOPN - 1])) return;
    int p = TOPN - 1;
    while (p > 0 && kbetter(v, e, bs[p - 1], bi[p - 1])) {
        bs[p] = bs[p - 1]; bi[p] = bi[p - 1]; p--;
    }
    bs[p] = v; bi[p] = e;
}

__global__ void k_top_a() {
    float bs[TOPN]; int bi[TOPN];
#pragma unroll
    for (int j = 0; j < TOPN; j++) { bs[j] = -1e30f; bi[j] = 0x7fffffff; }
    int t = blockIdx.x * 256 + threadIdx.x;
    for (int e = t; e < NEDGE; e += 128 * 256) {
        top_insert(bs, bi, g_scores[e], e);
    }
    __shared__ float ss[256 * TOPN];
    __shared__ int si[256 * TOPN];
#pragma unroll
    for (int j = 0; j < TOPN; j++) {
        ss[threadIdx.x * TOPN + j] = bs[j];
        si[threadIdx.x * TOPN + j] = bi[j];
    }
    __syncthreads();
    if (threadIdx.x == 0) {
        float cs[TOPN]; int ci[TOPN];
#pragma unroll
        for (int j = 0; j < TOPN; j++) { cs[j] = -1e30f; ci[j] = 0x7fffffff; }
        for (int k = 0; k < 256 * TOPN; k++) top_insert(cs, ci, ss[k], si[k]);
        for (int j = 0; j < TOPN; j++) {
            g_cs[blockIdx.x * TOPN + j] = cs[j];
            g_ci[blockIdx.x * TOPN + j] = ci[j];
        }
    }
}

__global__ void k_top_b(float* __restrict__ out) {
    if (threadIdx.x == 0) {
        float cs[TOPN]; int ci[TOPN];
#pragma unroll
        for (int j = 0; j < TOPN; j++) { cs[j] = -1e30f; ci[j] = 0x7fffffff; }
        for (int k = 0; k < 128 * TOPN; k++) top_insert(cs, ci, g_cs[k], g_ci[k]);
        for (int j = 0; j < TOPN; j++) {
            out[(size_t)NSRC * DIM + j] = cs[j];
            out[(size_t)NSRC * DIM + TOPN + j] = (float)ci[j];
        }
    }
}

// ---------------- host entry -------------------------------------------------
extern "C" void kernel_launch(void* const* d_in, const int* in_sizes, int n_in,
                              void* d_out, int out_size) {
    bool dictorder = (in_sizes[2] == NEDGE);
    const float* paths = (const float*)d_in[0];
    const float* pf    = (const float*)d_in[1];
    const int*   sid   = (const int*)d_in[dictorder ? 2 : 19];
    int b = dictorder ? 3 : 2;
    const float* cew = (const float*)d_in[b + 0];
    const float* ceb = (const float*)d_in[b + 1];
    const float* w1  = (const float*)d_in[b + 2];
    const float* bng = (const float*)d_in[b + 3];
    const float* bnb = (const float*)d_in[b + 4];
    const float* w2  = (const float*)d_in[b + 5];
    const float* l1W = (const float*)d_in[b + 6];
    const float* l1b = (const float*)d_in[b + 7];
    const float* l2W = (const float*)d_in[b + 8];
    const float* l2b = (const float*)d_in[b + 9];
    const float* psW = (const float*)d_in[b + 10];
    const float* psb = (const float*)d_in[b + 11];
    const float* ptW = (const float*)d_in[b + 12];
    const float* ptb = (const float*)d_in[b + 13];
    const float* peg = (const float*)d_in[b + 14];
    const float* peb = (const float*)d_in[b + 15];
    const float* sw  = (const float*)d_in[b + 16];
    float* out = (float*)d_out;

    void *p_agg, *p_Wc, *p_Wei1, *p_T, *p_cvec;
    void *p_Wbh, *p_Wbl, *p_Wch, *p_Wcl, *p_l2h, *p_l2l, *p_psh, *p_psl;
    cudaGetSymbolAddress(&p_agg, g_agg);
    cudaGetSymbolAddress(&p_Wc, g_Wc);
    cudaGetSymbolAddress(&p_Wei1, g_Wei1);
    cudaGetSymbolAddress(&p_T, g_T);
    cudaGetSymbolAddress(&p_cvec, g_cvec);
    cudaGetSymbolAddress(&p_Wbh, g_Wbh);
    cudaGetSymbolAddress(&p_Wbl, g_Wbl);
    cudaGetSymbolAddress(&p_Wch, g_Wch);
    cudaGetSymbolAddress(&p_Wcl, g_Wcl);
    cudaGetSymbolAddress(&p_l2h, g_l2h);
    cudaGetSymbolAddress(&p_l2l, g_l2l);
    cudaGetSymbolAddress(&p_psh, g_psh);
    cudaGetSymbolAddress(&p_psl, g_psl);
    const __nv_bfloat16* Wbh = (const __nv_bfloat16*)p_Wbh;
    const __nv_bfloat16* Wbl = (const __nv_bfloat16*)p_Wbl;
    const __nv_bfloat16* Wch = (const __nv_bfloat16*)p_Wch;
    const __nv_bfloat16* Wcl = (const __nv_bfloat16*)p_Wcl;
    const __nv_bfloat16* l2h = (const __nv_bfloat16*)p_l2h;
    const __nv_bfloat16* l2l = (const __nv_bfloat16*)p_l2l;
    const __nv_bfloat16* psh = (const __nv_bfloat16*)p_psh;
    const __nv_bfloat16* psl = (const __nv_bfloat16*)p_psl;

    cudaFuncSetAttribute(k_edge_gemm, cudaFuncAttributeMaxDynamicSharedMemorySize, EG_SMEM);
    cudaFuncSetAttribute(k_ncat, cudaFuncAttributeMaxDynamicSharedMemorySize, NC_SMEM);
    cudaFuncSetAttribute(k_nfused, cudaFuncAttributeMaxDynamicSharedMemorySize, NF_SMEM);

    const int NODE_BLKS = (NSRC + 127) / 128;   // 79

    k_reset<<<40, 256>>>();
    k_hist<<<(NEDGE + 255) / 256, 256>>>(sid);
    k_scan<<<1, 1024>>>();
    k_scatter<<<(NEDGE + 255) / 256, 256>>>(sid);
    k_prepB<<<128, 256>>>(ptW);
    k_agg<<<(NSRC * 32 + 255) / 256, 256>>>(pf);

    gemm128<<<dim3(1, 3), 256>>>(w2, DIM, DIM, DIM, (long)DIM * DIM,
                                 l1W, (long)DIM * DIM, (float*)p_Wc, (long)DIM * DIM);
    gemm128<<<dim3(2, 3), 256>>>(cew, EDIM, DIM, DIM, (long)EDIM * DIM,
                                 w1, (long)DIM * DIM, (float*)p_Wei1, (long)EDIM * DIM);
    k_cvec<<<3, 128>>>(ceb, w1);

    k_prepWbig<<<dim3(192, 3), 256>>>(w1);
    k_prepWgen<<<192, 256>>>((const float*)p_Wc, (__nv_bfloat16*)p_Wch,
                             (__nv_bfloat16*)p_Wcl, 384, 384);
    k_prepWgen<<<64, 256>>>(l2W, (__nv_bfloat16*)p_l2h, (__nv_bfloat16*)p_l2l, 128, 128);
    k_prepWgen<<<64, 256>>>(psW, (__nv_bfloat16*)p_psh, (__nv_bfloat16*)p_psl, 128, 128);

    // T_cat = [agg|paths] @ Wbig_i + c_i  (+ BN stats)
    k_ncat<<<dim3(NODE_BLKS, 3), 256, NC_SMEM>>>(
        (const float*)p_agg, paths, Wbh, Wbl, (const float*)p_cvec, (float*)p_T);
    k_coef1<<<2, 256>>>(bng, bnb, psb, ptb);

    // fused: h2 -> node_emb(out) -> srcterm, one launch
    k_nfused<<<NODE_BLKS, 256, NF_SMEM>>>(l1b, l2b, Wch, Wcl, l2h, l2l, psh, psl, out);

    // edge GEMM (fp16 single-product) with fused srcterm add + BN stats
    k_edge_gemm<<<NEDGE / 128, 256, EG_SMEM>>>(pf, sid);

    k_coef2<<<1, 128>>>(peg, peb);
    k_scores<<<NEDGE / 512, 256>>>(sw);
    k_top_a<<<128, 256>>>();
    k_top_b<<<1, 32>>>(out);
}

// round 17
// speedup vs baseline: 1.2120x; 1.1066x over previous
#include <cuda_runtime.h>
#include <cuda_bf16.h>
#include <cuda_fp16.h>
#include <math.h>
#include <stdint.h>

#define NSRC 10000
#define NEDGE 320000
#define DIM 128
#define EDIM 236
#define TOPN 6
#define BN_EPS 1e-5f

// ---------------- scratch (device globals; no allocation allowed) ----------
__device__ float  g_agg[(size_t)NSRC * EDIM];
__device__ __half g_xg[(size_t)NEDGE * DIM];         // y = xg + srcterm[sid], fp16
__device__ float  g_srcterm[(size_t)NSRC * DIM];
__device__ float  g_T[(size_t)3 * NSRC * DIM];
__device__ float  g_Wc[3 * DIM * DIM];
__device__ float  g_Wei1[3 * EDIM * DIM];
__device__ float  g_cvec[3 * DIM];
__device__ float  g_scores[NEDGE];
__device__ int    g_cnt[NSRC];
__device__ int    g_off[NSRC + 1];
__device__ int    g_cur[NSRC];
__device__ int    g_order[NEDGE];
__device__ double g_tsum[3 * DIM], g_tsumsq[3 * DIM];
__device__ double g_psumB[32 * DIM], g_psumsqB[32 * DIM];
__device__ float  g_ta[3 * DIM], g_tc[3 * DIM];
__device__ float  g_peA[DIM], g_peC[DIM];
__device__ float  g_combB[DIM];
__device__ float  g_cs[128 * TOPN];
__device__ int    g_ci[128 * TOPN];
// pre-converted weights
__device__ __half        g_Bf[128 * 256];                       // pe_tgt_W fp16, n-major
__device__ __nv_bfloat16 g_Wbh[3 * 128 * 384], g_Wbl[3 * 128 * 384]; // Wbig split-bf16
__device__ __nv_bfloat16 g_Wch[128 * 384], g_Wcl[128 * 384];
__device__ __nv_bfloat16 g_l2h[128 * 128], g_l2l[128 * 128];
__device__ __nv_bfloat16 g_psh[128 * 128], g_psl[128 * 128];

// ---------------- small utility kernels ------------------------------------
__global__ void k_reset() {
    int t = blockIdx.x * blockDim.x + threadIdx.x;
    if (t < NSRC) g_cnt[t] = 0;
    if (t < 3 * DIM) { g_tsum[t] = 0.0; g_tsumsq[t] = 0.0; }
    if (t < 32 * DIM) { g_psumB[t] = 0.0; g_psumsqB[t] = 0.0; }
}

__global__ void k_hist(const int* __restrict__ sid) {
    int e = blockIdx.x * blockDim.x + threadIdx.x;
    if (e < NEDGE) atomicAdd(&g_cnt[sid[e]], 1);
}

__global__ void k_scan() {
    __shared__ int s[1024];
    int t = threadIdx.x;
    int base = t * 10;
    int loc[10];
    int acc = 0;
#pragma unroll
    for (int j = 0; j < 10; j++) {
        int idx = base + j;
        int v = (idx < NSRC) ? g_cnt[idx] : 0;
        loc[j] = acc; acc += v;
    }
    s[t] = acc;
    __syncthreads();
    for (int off = 1; off < 1024; off <<= 1) {
        int v = (t >= off) ? s[t - off] : 0;
        __syncthreads();
        s[t] += v;
        __syncthreads();
    }
    int pre = (t > 0) ? s[t - 1] : 0;
#pragma unroll
    for (int j = 0; j < 10; j++) {
        int idx = base + j;
        if (idx < NSRC) { g_off[idx] = pre + loc[j]; g_cur[idx] = pre + loc[j]; }
    }
    if (t == 0) g_off[NSRC] = NEDGE;
}

__global__ void k_scatter(const int* __restrict__ sid) {
    int e = blockIdx.x * blockDim.x + threadIdx.x;
    if (e < NEDGE) {
        int p = atomicAdd(&g_cur[sid[e]], 1);
        g_order[p] = e;
    }
}

__device__ __forceinline__ void splitbf(float v, __nv_bfloat16& h, __nv_bfloat16& l) {
    h = __float2bfloat16(v);
    l = __float2bfloat16(v - __bfloat162float(h));
}

// edge-B prep: pe_tgt_W[236,128] -> fp16, n-major [n][256]
__global__ void k_prepB(const float* __restrict__ ptW) {
    int idx = blockIdx.x * 256 + threadIdx.x;
    if (idx >= 128 * 256) return;
    int k = idx >> 7, n = idx & 127;
    float b = (k < EDIM) ? ptW[(size_t)k * DIM + n] : 0.f;
    g_Bf[n * 256 + k] = __float2half_rn(b);
}

__global__ void k_prepWbig(const float* __restrict__ w1) {
    int i = blockIdx.y;
    int idx = blockIdx.x * 256 + threadIdx.x;
    int n = idx / 384, k = idx % 384;
    float v = 0.f;
    if (k < EDIM) v = g_Wei1[i * EDIM * DIM + k * DIM + n];
    else if (k < EDIM + DIM) v = w1[i * DIM * DIM + (k - EDIM) * DIM + n];
    __nv_bfloat16 h, l; splitbf(v, h, l);
    g_Wbh[i * 128 * 384 + n * 384 + k] = h;
    g_Wbl[i * 128 * 384 + n * 384 + k] = l;
}

__global__ void k_prepWgen(const float* __restrict__ src, __nv_bfloat16* __restrict__ dh,
                           __nv_bfloat16* __restrict__ dl, int K, int Kpad) {
    int idx = blockIdx.x * 256 + threadIdx.x;
    if (idx >= 128 * Kpad) return;
    int n = idx / Kpad, k = idx % Kpad;
    float v = (k < K) ? src[(size_t)k * DIM + n] : 0.f;
    __nv_bfloat16 h, l; splitbf(v, h, l);
    dh[n * Kpad + k] = h;
    dl[n * Kpad + k] = l;
}

__global__ void k_cvec(const float* __restrict__ ceb, const float* __restrict__ w1) {
    int i = blockIdx.x, n = threadIdx.x;
    float s = 0.f;
    for (int k = 0; k < DIM; k++)
        s += ceb[i * DIM + k] * w1[i * DIM * DIM + k * DIM + n];
    g_cvec[i * DIM + n] = s;
}

__global__ void k_agg(const float* __restrict__ pf) {
    int w = (blockIdx.x * blockDim.x + threadIdx.x) >> 5;
    int lane = threadIdx.x & 31;
    if (w >= NSRC) return;
    float4 a0 = make_float4(0.f, 0.f, 0.f, 0.f);
    float4 a1 = make_float4(0.f, 0.f, 0.f, 0.f);
    int s = g_off[w], e2 = g_off[w + 1];
    for (int p = s; p < e2; p++) {
        const float4* r = (const float4*)(pf + (size_t)g_order[p] * EDIM);
        float4 v = __ldg(r + lane);
        a0.x += fmaxf(v.x, 0.f); a0.y += fmaxf(v.y, 0.f);
        a0.z += fmaxf(v.z, 0.f); a0.w += fmaxf(v.w, 0.f);
        if (lane < 27) {
            float4 v2 = __ldg(r + 32 + lane);
            a1.x += fmaxf(v2.x, 0.f); a1.y += fmaxf(v2.y, 0.f);
            a1.z += fmaxf(v2.z, 0.f); a1.w += fmaxf(v2.w, 0.f);
        }
    }
    float4* outp = (float4*)(g_agg + (size_t)w * EDIM);
    outp[lane] = a0;
    if (lane < 27) outp[32 + lane] = a1;
}

// ---------------- small fp32 GEMM (C = A@W), batched over blockIdx.y --------
__global__ void __launch_bounds__(256)
gemm128(const float* __restrict__ A, int M, int K, int lda, long astr,
        const float* __restrict__ W, long wstr,
        float* __restrict__ C, long cstr) {
    int bz = blockIdx.y;
    A += (size_t)bz * astr;
    W += (size_t)bz * wstr;
    C += (size_t)bz * cstr;

    __shared__ float sA[8][128];
    __shared__ float sW[8][128];
    int tid = threadIdx.x;
    int row0 = blockIdx.x * 128;
    int tx = tid & 15, ty = tid >> 4;
    float acc[8][8];
#pragma unroll
    for (int i = 0; i < 8; i++)
#pragma unroll
        for (int j = 0; j < 8; j++) acc[i][j] = 0.f;

    int ar = tid >> 1;
    int ac = (tid & 1) * 4;
    int wk = (tid * 4) >> 7;
    int wc = (tid * 4) & 127;

    for (int kk = 0; kk < K; kk += 8) {
        float4 av = make_float4(0.f, 0.f, 0.f, 0.f);
        int grow = row0 + ar;
        if (grow < M) {
            int k = kk + ac;
            if (k + 3 < K) {
                av = *(const float4*)(A + (size_t)grow * lda + k);
            } else {
#pragma unroll
                for (int j = 0; j < 4; j++) {
                    int kj = k + j;
                    ((float*)&av)[j] = (kj < K) ? A[(size_t)grow * lda + kj] : 0.f;
                }
            }
        }
        sA[ac + 0][ar] = av.x; sA[ac + 1][ar] = av.y;
        sA[ac + 2][ar] = av.z; sA[ac + 3][ar] = av.w;

        float4 wv = make_float4(0.f, 0.f, 0.f, 0.f);
        if (kk + wk < K) wv = *(const float4*)(W + (size_t)(kk + wk) * 128 + wc);
        *(float4*)&sW[wk][wc] = wv;
        __syncthreads();

#pragma unroll
        for (int k = 0; k < 8; k++) {
            float4 a0 = *(float4*)&sA[k][ty * 8];
            float4 a1 = *(float4*)&sA[k][ty * 8 + 4];
            float4 b0 = *(float4*)&sW[k][tx * 8];
            float4 b1 = *(float4*)&sW[k][tx * 8 + 4];
            float ra[8] = {a0.x, a0.y, a0.z, a0.w, a1.x, a1.y, a1.z, a1.w};
            float rb[8] = {b0.x, b0.y, b0.z, b0.w, b1.x, b1.y, b1.z, b1.w};
#pragma unroll
            for (int i = 0; i < 8; i++)
#pragma unroll
                for (int j = 0; j < 8; j++) acc[i][j] += ra[i] * rb[j];
        }
        __syncthreads();
    }
#pragma unroll
    for (int i = 0; i < 8; i++) {
        int row = row0 + ty * 8 + i;
        if (row < M)
#pragma unroll
            for (int j = 0; j < 8; j++)
                C[(size_t)row * DIM + tx * 8 + j] = acc[i][j];
    }
}

// =================== shared MMA machinery ===================================
#define LDE 72
#define LDW 36
#define ROWB 144
#define TILEB (128 * ROWB)
#define EG_SMEM (2 * TILEB)
#define NC_SMEM (4 * TILEB)
#define NF_SMEM (6 * TILEB)

__device__ __forceinline__ void mma_bf16(float* c, const uint32_t* a, const uint32_t* b) {
    asm volatile(
        "mma.sync.aligned.m16n8k16.row.col.f32.bf16.bf16.f32 "
        "{%0,%1,%2,%3}, {%4,%5,%6,%7}, {%8,%9}, {%0,%1,%2,%3};"
        : "+f"(c[0]), "+f"(c[1]), "+f"(c[2]), "+f"(c[3])
        : "r"(a[0]), "r"(a[1]), "r"(a[2]), "r"(a[3]), "r"(b[0]), "r"(b[1]));
}
__device__ __forceinline__ void mma_f16(float* c, const uint32_t* a, const uint32_t* b) {
    asm volatile(
        "mma.sync.aligned.m16n8k16.row.col.f32.f16.f16.f32 "
        "{%0,%1,%2,%3}, {%4,%5,%6,%7}, {%8,%9}, {%0,%1,%2,%3};"
        : "+f"(c[0]), "+f"(c[1]), "+f"(c[2]), "+f"(c[3])
        : "r"(a[0]), "r"(a[1]), "r"(a[2]), "r"(a[3]), "r"(b[0]), "r"(b[1]));
}
__device__ __forceinline__ void ldsm4(uint32_t* r, uint32_t a) {
    asm volatile("ldmatrix.sync.aligned.m8n8.x4.shared.b16 {%0,%1,%2,%3}, [%4];"
                 : "=r"(r[0]), "=r"(r[1]), "=r"(r[2]), "=r"(r[3]) : "r"(a));
}
__device__ __forceinline__ uint32_t packbf(float x, float y) {
    union { __nv_bfloat162 b; uint32_t u; } c;
    c.b = __float22bfloat162_rn(make_float2(x, y));
    return c.u;
}
__device__ __forceinline__ uint32_t packh(float x, float y) {
    union { __half2 h; uint32_t u; } c;
    c.h = __floats2half2_rn(x, y);
    return c.u;
}
__device__ __forceinline__ void split_pair(float y0, float y1, uint32_t& h, uint32_t& l) {
    h = packbf(y0, y1);
    float r0 = y0 - __bfloat162float(__ushort_as_bfloat16((uint16_t)h));
    float r1 = y1 - __bfloat162float(__ushort_as_bfloat16((uint16_t)(h >> 16)));
    l = packbf(r0, r1);
}

__device__ __forceinline__ uint32_t a_ldsm_off(int lane, int warpM) {
    int row = warpM * 64 + (lane & 7) + ((lane >> 3) & 1) * 8;
    return (uint32_t)row * ROWB + (uint32_t)((lane >> 4) & 1) * 16;
}
__device__ __forceinline__ uint32_t b_ldsm_off(int lane, int warpN) {
    int row = warpN * 32 + ((lane >> 4) & 1) * 8 + (lane & 7);
    return (uint32_t)row * ROWB + (uint32_t)((lane >> 3) & 1) * 16;
}

__device__ __forceinline__ void mma_chunk(uint32_t aH, uint32_t aL,
                                          uint32_t bH, uint32_t bL,
                                          float acc[4][4][4], int ksmax) {
    for (int ks = 0; ks < ksmax; ks++) {
        uint32_t kb = (uint32_t)ks * 32;
        uint32_t bh[8], bl[8];
        ldsm4(&bh[0], bH + kb);
        ldsm4(&bh[4], bH + 16 * ROWB + kb);
        ldsm4(&bl[0], bL + kb);
        ldsm4(&bl[4], bL + 16 * ROWB + kb);
#pragma unroll
        for (int mt = 0; mt < 4; mt++) {
            uint32_t ah[4], al[4];
            ldsm4(ah, aH + (uint32_t)mt * 16 * ROWB + kb);
            ldsm4(al, aL + (uint32_t)mt * 16 * ROWB + kb);
#pragma unroll
            for (int nt = 0; nt < 4; nt++) {
                mma_bf16(acc[mt][nt], ah, &bh[nt * 2]);
                mma_bf16(acc[mt][nt], ah, &bl[nt * 2]);
                mma_bf16(acc[mt][nt], al, &bh[nt * 2]);
            }
        }
    }
}

__device__ __forceinline__ void mma_chunk1(uint32_t aF, uint32_t bF,
                                           float acc[4][4][4], int ksmax) {
    for (int ks = 0; ks < ksmax; ks++) {
        uint32_t kb = (uint32_t)ks * 32;
        uint32_t bh[8];
        ldsm4(&bh[0], bF + kb);
        ldsm4(&bh[4], bF + 16 * ROWB + kb);
#pragma unroll
        for (int mt = 0; mt < 4; mt++) {
            uint32_t ah[4];
            ldsm4(ah, aF + (uint32_t)mt * 16 * ROWB + kb);
#pragma unroll
            for (int nt = 0; nt < 4; nt++)
                mma_f16(acc[mt][nt], ah, &bh[nt * 2]);
        }
    }
}

__device__ __forceinline__ void store_split(uint32_t* sAh, uint32_t* sAl, int w, float4 a) {
    uint32_t h01 = packbf(a.x, a.y), h23 = packbf(a.z, a.w);
    float fx = a.x - __bfloat162float(__ushort_as_bfloat16((uint16_t)h01));
    float fy = a.y - __bfloat162float(__ushort_as_bfloat16((uint16_t)(h01 >> 16)));
    uint32_t l01 = packbf(fx, fy);
    fx = a.z - __bfloat162float(__ushort_as_bfloat16((uint16_t)h23));
    fy = a.w - __bfloat162float(__ushort_as_bfloat16((uint16_t)(h23 >> 16)));
    uint32_t l23 = packbf(fx, fy);
    sAh[w] = h01; sAh[w + 1] = h23;
    sAl[w] = l01; sAl[w + 1] = l23;
}

// =================== edge GEMM (fp16 single-product) + fused epilogue =======
__global__ void __launch_bounds__(256, 2)
k_edge_gemm(const float* __restrict__ pf, const int* __restrict__ sid) {
    extern __shared__ char smem[];
    uint32_t sbase = (uint32_t)__cvta_generic_to_shared(smem);
    uint32_t* sAf = (uint32_t*)smem;
    uint32_t* sBf = sAf + 128 * LDW;
    int tid = threadIdx.x, wid = tid >> 5, lane = tid & 31;
    int g = lane >> 2, tg = lane & 3;
    int warpM = wid & 1, warpN = wid >> 1;
    int row0 = blockIdx.x * 128;

    uint32_t aF = sbase + a_ldsm_off(lane, warpM);
    uint32_t bF = sbase + TILEB + b_ldsm_off(lane, warpN);

    float acc[4][4][4];
#pragma unroll
    for (int mt = 0; mt < 4; mt++)
#pragma unroll
        for (int nt = 0; nt < 4; nt++)
#pragma unroll
            for (int j = 0; j < 4; j++) acc[mt][nt][j] = 0.f;

    for (int kk = 0; kk < 256; kk += 64) {
#pragma unroll
        for (int it = 0; it < 8; it++) {
            int idx = tid + it * 256;
            int r = idx >> 4, cq = idx & 15;
            int k = kk + cq * 4;
            float4 a = make_float4(0.f, 0.f, 0.f, 0.f);
            if (k + 3 < EDIM)
                a = *(const float4*)(pf + (size_t)(row0 + r) * EDIM + k);
            int w = r * LDW + cq * 2;
            sAf[w] = packh(a.x, a.y);
            sAf[w + 1] = packh(a.z, a.w);
        }
#pragma unroll
        for (int it = 0; it < 4; it++) {
            int idx = tid + it * 256;
            int n = idx >> 3, j = idx & 7;
            *(uint4*)(sBf + n * LDW + j * 4) =
                *(const uint4*)((const char*)g_Bf + ((size_t)n * 256 + kk + j * 8) * 2);
        }
        __syncthreads();
        int ksmax = (kk == 192) ? 3 : 4;   // k 240..255 is all zero padding
        mma_chunk1(aF, bF, acc, ksmax);
        __syncthreads();
    }

    // fused epilogue: y = acc + srcterm[sid[r]], store fp16, BN stats (fp32)
    float s_loc[4][2], q_loc[4][2];
#pragma unroll
    for (int nt = 0; nt < 4; nt++) {
        s_loc[nt][0] = s_loc[nt][1] = 0.f;
        q_loc[nt][0] = q_loc[nt][1] = 0.f;
    }
#pragma unroll
    for (int mt = 0; mt < 4; mt++) {
        int r0 = row0 + warpM * 64 + mt * 16 + g;
        const float* st0 = g_srcterm + (size_t)sid[r0] * DIM;
        const float* st1 = g_srcterm + (size_t)sid[r0 + 8] * DIM;
#pragma unroll
        for (int nt = 0; nt < 4; nt++) {
            int n = warpN * 32 + nt * 8 + 2 * tg;
            float2 e0 = *(const float2*)(st0 + n);
            float2 e1 = *(const float2*)(st1 + n);
            float y00 = acc[mt][nt][0] + e0.x, y01 = acc[mt][nt][1] + e0.y;
            float y10 = acc[mt][nt][2] + e1.x, y11 = acc[mt][nt][3] + e1.y;
            *(uint32_t*)((__half*)g_xg + (size_t)r0 * DIM + n) = packh(y00, y01);
            *(uint32_t*)((__half*)g_xg + (size_t)(r0 + 8) * DIM + n) = packh(y10, y11);
            s_loc[nt][0] += y00 + y10; s_loc[nt][1] += y01 + y11;
            q_loc[nt][0] += y00 * y00 + y10 * y10;
            q_loc[nt][1] += y01 * y01 + y11 * y11;
        }
    }
    __syncthreads();
    float* sS = (float*)smem;
    float* sQ = sS + 128;
    if (tid < 128) { sS[tid] = 0.f; sQ[tid] = 0.f; }
    __syncthreads();
#pragma unroll
    for (int nt = 0; nt < 4; nt++) {
        int n = warpN * 32 + nt * 8 + 2 * tg;
        atomicAdd(&sS[n], s_loc[nt][0]);
        atomicAdd(&sS[n + 1], s_loc[nt][1]);
        atomicAdd(&sQ[n], q_loc[nt][0]);
        atomicAdd(&sQ[n + 1], q_loc[nt][1]);
    }
    __syncthreads();
    if (tid < 128) {
        int bkt = (blockIdx.x & 31) * DIM + tid;
        atomicAdd(&g_psumB[bkt], (double)sS[tid]);
        atomicAdd(&g_psumsqB[bkt], (double)sQ[tid]);
    }
}

// =================== T_cat node GEMM (split-bf16, BN stats) =================
__global__ void __launch_bounds__(256, 2)
k_ncat(const float* __restrict__ A1, const float* __restrict__ A2,
       const __nv_bfloat16* __restrict__ Wh, const __nv_bfloat16* __restrict__ Wl,
       const float* __restrict__ bias, float* __restrict__ C) {
    int bz = blockIdx.y;
    Wh += (size_t)bz * 128 * 384; Wl += (size_t)bz * 128 * 384;
    bias += (size_t)bz * DIM; C += (size_t)bz * NSRC * DIM;

    extern __shared__ char smem[];
    uint32_t sbase = (uint32_t)__cvta_generic_to_shared(smem);
    uint32_t* sAh = (uint32_t*)smem;
    uint32_t* sAl = sAh + 128 * LDW;
    uint32_t* sBh = sAl + 128 * LDW;
    uint32_t* sBl = sBh + 128 * LDW;
    int tid = threadIdx.x, wid = tid >> 5, lane = tid & 31;
    int g = lane >> 2, tg = lane & 3;
    int warpM = wid & 1, warpN = wid >> 1;
    int row0 = blockIdx.x * 128;

    uint32_t aoff = a_ldsm_off(lane, warpM);
    uint32_t boff = b_ldsm_off(lane, warpN);
    uint32_t aH = sbase + aoff,            aL = sbase + TILEB + aoff;
    uint32_t bH = sbase + 2 * TILEB + boff, bL = sbase + 3 * TILEB + boff;

    float acc[4][4][4];
#pragma unroll
    for (int mt = 0; mt < 4; mt++)
#pragma unroll
        for (int nt = 0; nt < 4; nt++)
#pragma unroll
            for (int j = 0; j < 4; j++) acc[mt][nt][j] = 0.f;

    for (int kk = 0; kk < 384; kk += 64) {
#pragma unroll
        for (int it = 0; it < 8; it++) {
            int idx = tid + it * 256;
            int r = idx >> 4, cq = idx & 15;
            int k = kk + cq * 4;
            int grow = row0 + r;
            float4 a = make_float4(0.f, 0.f, 0.f, 0.f);
            if (grow < NSRC) {
                if (k < EDIM) a = *(const float4*)(A1 + (size_t)grow * EDIM + k);
                else if (k < EDIM + DIM) a = *(const float4*)(A2 + (size_t)grow * DIM + (k - EDIM));
            }
            store_split(sAh, sAl, r * LDW + cq * 2, a);
        }
#pragma unroll
        for (int it = 0; it < 4; it++) {
            int idx = tid + it * 256;
            int n = idx >> 3, j = idx & 7;
            const char* srch = (const char*)Wh + ((size_t)n * 384 + kk + j * 8) * 2;
            const char* srcl = (const char*)Wl + ((size_t)n * 384 + kk + j * 8) * 2;
            *(uint4*)(sBh + n * LDW + j * 4) = *(const uint4*)srch;
            *(uint4*)(sBl + n * LDW + j * 4) = *(const uint4*)srcl;
        }
        __syncthreads();
        int rem = (364 - kk + 15) >> 4;
        int ksmax = rem < 4 ? rem : 4;
        mma_chunk(aH, aL, bH, bL, acc, ksmax);
        __syncthreads();
    }

    float s_loc[4][2], q_loc[4][2];
#pragma unroll
    for (int nt = 0; nt < 4; nt++) {
        s_loc[nt][0] = s_loc[nt][1] = 0.f;
        q_loc[nt][0] = q_loc[nt][1] = 0.f;
    }
#pragma unroll
    for (int mt = 0; mt < 4; mt++) {
        int r0 = row0 + warpM * 64 + mt * 16 + g;
        bool v0 = r0 < NSRC, v1 = (r0 + 8) < NSRC;
#pragma unroll
        for (int nt = 0; nt < 4; nt++) {
            int n = warpN * 32 + nt * 8 + 2 * tg;
            float b0 = bias[n], b1 = bias[n + 1];
            float y00 = acc[mt][nt][0] + b0, y01 = acc[mt][nt][1] + b1;
            float y10 = acc[mt][nt][2] + b0, y11 = acc[mt][nt][3] + b1;
            if (v0) *(float2*)(C + (size_t)r0 * DIM + n) = make_float2(y00, y01);
            if (v1) *(float2*)(C + (size_t)(r0 + 8) * DIM + n) = make_float2(y10, y11);
            if (v0) { s_loc[nt][0] += y00; s_loc[nt][1] += y01;
                      q_loc[nt][0] += y00 * y00; q_loc[nt][1] += y01 * y01; }
            if (v1) { s_loc[nt][0] += y10; s_loc[nt][1] += y11;
                      q_loc[nt][0] += y10 * y10; q_loc[nt][1] += y11 * y11; }
        }
    }
    __syncthreads();
    float* sS = (float*)smem;
    float* sQ = sS + 128;
    if (tid < 128) { sS[tid] = 0.f; sQ[tid] = 0.f; }
    __syncthreads();
#pragma unroll
    for (int nt = 0; nt < 4; nt++) {
        int n = warpN * 32 + nt * 8 + 2 * tg;
        atomicAdd(&sS[n], s_loc[nt][0]);
        atomicAdd(&sS[n + 1], s_loc[nt][1]);
        atomicAdd(&sQ[n], q_loc[nt][0]);
        atomicAdd(&sQ[n + 1], q_loc[nt][1]);
    }
    __syncthreads();
    if (tid < 128) {
        atomicAdd(&g_tsum[bz * DIM + tid], (double)sS[tid]);
        atomicAdd(&g_tsumsq[bz * DIM + tid], (double)sQ[tid]);
    }
}

// =================== fused node chain: h2 -> node_emb -> srcterm ============
__global__ void __launch_bounds__(256, 1)
k_nfused(const float* __restrict__ l1b, const float* __restrict__ l2b,
         const __nv_bfloat16* __restrict__ Wch, const __nv_bfloat16* __restrict__ Wcl,
         const __nv_bfloat16* __restrict__ l2h, const __nv_bfloat16* __restrict__ l2l,
         const __nv_bfloat16* __restrict__ psh, const __nv_bfloat16* __restrict__ psl,
         float* __restrict__ out) {
    extern __shared__ char smem[];
    uint32_t sbase = (uint32_t)__cvta_generic_to_shared(smem);
    uint32_t* wA0h = (uint32_t*)smem;
    uint32_t* wA0l = wA0h + TILEB / 4;
    uint32_t* wA1h = wA0h + 2 * (TILEB / 4);
    uint32_t* wA1l = wA0h + 3 * (TILEB / 4);
    uint32_t* wBh  = wA0h + 4 * (TILEB / 4);
    uint32_t* wBl  = wA0h + 5 * (TILEB / 4);
    int tid = threadIdx.x, wid = tid >> 5, lane = tid & 31;
    int g = lane >> 2, tg = lane & 3;
    int warpM = wid & 1, warpN = wid >> 1;
    int row0 = blockIdx.x * 128;

    uint32_t aoff = a_ldsm_off(lane, warpM);
    uint32_t boff = b_ldsm_off(lane, warpN);
    uint32_t A0H = sbase + aoff,             A0L = sbase + TILEB + aoff;
    uint32_t A1H = sbase + 2 * TILEB + aoff, A1L = sbase + 3 * TILEB + aoff;
    uint32_t BH  = sbase + 4 * TILEB + boff, BL  = sbase + 5 * TILEB + boff;

    float acc[4][4][4];
#pragma unroll
    for (int mt = 0; mt < 4; mt++)
#pragma unroll
        for (int nt = 0; nt < 4; nt++)
#pragma unroll
            for (int j = 0; j < 4; j++) acc[mt][nt][j] = 0.f;

    // ---- stage 1: h2 = relu(Z @ Wc + l1b); Z = relu(ta*T + tc); K=384 ----
    for (int kk = 0; kk < 384; kk += 64) {
#pragma unroll
        for (int it = 0; it < 8; it++) {
            int idx = tid + it * 256;
            int r = idx >> 4, cq = idx & 15;
            int k = kk + cq * 4;
            int grow = row0 + r;
            float4 a = make_float4(0.f, 0.f, 0.f, 0.f);
            if (grow < NSRC) {
                int blk = k >> 7;
                float4 t = *(const float4*)(g_T + ((size_t)(blk * NSRC + grow)) * DIM + (k & 127));
                float4 ta = *(const float4*)(g_ta + k);
                float4 tc = *(const float4*)(g_tc + k);
                a.x = fmaxf(ta.x * t.x + tc.x, 0.f);
                a.y = fmaxf(ta.y * t.y + tc.y, 0.f);
                a.z = fmaxf(ta.z * t.z + tc.z, 0.f);
                a.w = fmaxf(ta.w * t.w + tc.w, 0.f);
            }
            store_split(wA0h, wA0l, r * LDW + cq * 2, a);
        }
#pragma unroll
        for (int it = 0; it < 4; it++) {
            int idx = tid + it * 256;
            int n = idx >> 3, j = idx & 7;
            *(uint4*)(wBh + n * LDW + j * 4) =
                *(const uint4*)((const char*)Wch + ((size_t)n * 384 + kk + j * 8) * 2);
            *(uint4*)(wBl + n * LDW + j * 4) =
                *(const uint4*)((const char*)Wcl + ((size_t)n * 384 + kk + j * 8) * 2);
        }
        __syncthreads();
        mma_chunk(A0H, A0L, BH, BL, acc, 4);
        __syncthreads();
    }
#pragma unroll
    for (int mt = 0; mt < 4; mt++) {
        int rr0 = warpM * 64 + mt * 16 + g;
#pragma unroll
        for (int nt = 0; nt < 4; nt++) {
            int col = warpN * 32 + nt * 8 + 2 * tg;
            float b0 = l1b[col], b1 = l1b[col + 1];
            float y00 = fmaxf(acc[mt][nt][0] + b0, 0.f);
            float y01 = fmaxf(acc[mt][nt][1] + b1, 0.f);
            float y10 = fmaxf(acc[mt][nt][2] + b0, 0.f);
            float y11 = fmaxf(acc[mt][nt][3] + b1, 0.f);
            uint32_t* dh = (col < 64) ? wA0h : wA1h;
            uint32_t* dl = (col < 64) ? wA0l : wA1l;
            int wofs = (col & 63) >> 1;
            uint32_t h, l;
            split_pair(y00, y01, h, l);
            dh[rr0 * LDW + wofs] = h; dl[rr0 * LDW + wofs] = l;
            split_pair(y10, y11, h, l);
            dh[(rr0 + 8) * LDW + wofs] = h; dl[(rr0 + 8) * LDW + wofs] = l;
        }
    }
    __syncthreads();

    // ---- stage 2: node_emb = h2 @ l2 + l2b (K=128, 2 chunks) ----
#pragma unroll
    for (int mt = 0; mt < 4; mt++)
#pragma unroll
        for (int nt = 0; nt < 4; nt++)
#pragma unroll
            for (int j = 0; j < 4; j++) acc[mt][nt][j] = 0.f;
    for (int c = 0; c < 2; c++) {
#pragma unroll
        for (int it = 0; it < 4; it++) {
            int idx = tid + it * 256;
            int n = idx >> 3, j = idx & 7;
            *(uint4*)(wBh + n * LDW + j * 4) =
                *(const uint4*)((const char*)l2h + ((size_t)n * 128 + c * 64 + j * 8) * 2);
            *(uint4*)(wBl + n * LDW + j * 4) =
                *(const uint4*)((const char*)l2l + ((size_t)n * 128 + c * 64 + j * 8) * 2);
        }
        __syncthreads();
        mma_chunk(c ? A1H : A0H, c ? A1L : A0L, BH, BL, acc, 4);
        __syncthreads();
    }
#pragma unroll
    for (int mt = 0; mt < 4; mt++) {
        int rr0 = warpM * 64 + mt * 16 + g;
        int gr0 = row0 + rr0;
#pragma unroll
        for (int nt = 0; nt < 4; nt++) {
            int col = warpN * 32 + nt * 8 + 2 * tg;
            float b0 = l2b[col], b1 = l2b[col + 1];
            float y00 = acc[mt][nt][0] + b0, y01 = acc[mt][nt][1] + b1;
            float y10 = acc[mt][nt][2] + b0, y11 = acc[mt][nt][3] + b1;
            if (gr0 < NSRC)
                *(float2*)(out + (size_t)gr0 * DIM + col) = make_float2(y00, y01);
            if (gr0 + 8 < NSRC)
                *(float2*)(out + (size_t)(gr0 + 8) * DIM + col) = make_float2(y10, y11);
            uint32_t* dh = (col < 64) ? wA0h : wA1h;
            uint32_t* dl = (col < 64) ? wA0l : wA1l;
            int wofs = (col & 63) >> 1;
            uint32_t h, l;
            split_pair(y00, y01, h, l);
            dh[rr0 * LDW + wofs] = h; dl[rr0 * LDW + wofs] = l;
            split_pair(y10, y11, h, l);
            dh[(rr0 + 8) * LDW + wofs] = h; dl[(rr0 + 8) * LDW + wofs] = l;
        }
    }
    __syncthreads();

    // ---- stage 3: srcterm = node_emb @ ps + combB (K=128, 2 chunks) ----
#pragma unroll
    for (int mt = 0; mt < 4; mt++)
#pragma unroll
        for (int nt = 0; nt < 4; nt++)
#pragma unroll
            for (int j = 0; j < 4; j++) acc[mt][nt][j] = 0.f;
    for (int c = 0; c < 2; c++) {
#pragma unroll
        for (int it = 0; it < 4; it++) {
            int idx = tid + it * 256;
            int n = idx >> 3, j = idx & 7;
            *(uint4*)(wBh + n * LDW + j * 4) =
                *(const uint4*)((const char*)psh + ((size_t)n * 128 + c * 64 + j * 8) * 2);
            *(uint4*)(wBl + n * LDW + j * 4) =
                *(const uint4*)((const char*)psl + ((size_t)n * 128 + c * 64 + j * 8) * 2);
        }
        __syncthreads();
        mma_chunk(c ? A1H : A0H, c ? A1L : A0L, BH, BL, acc, 4);
        __syncthreads();
    }
#pragma unroll
    for (int mt = 0; mt < 4; mt++) {
        int gr0 = row0 + warpM * 64 + mt * 16 + g;
#pragma unroll
        for (int nt = 0; nt < 4; nt++) {
            int col = warpN * 32 + nt * 8 + 2 * tg;
            float b0 = g_combB[col], b1 = g_combB[col + 1];
            if (gr0 < NSRC)
                *(float2*)(g_srcterm + (size_t)gr0 * DIM + col) =
                    make_float2(acc[mt][nt][0] + b0, acc[mt][nt][1] + b1);
            if (gr0 + 8 < NSRC)
                *(float2*)(g_srcterm + (size_t)(gr0 + 8) * DIM + col) =
                    make_float2(acc[mt][nt][2] + b0, acc[mt][nt][3] + b1);
        }
    }
}

// ---------------- BN coefficient finalization -------------------------------
__global__ void k_coef1(const float* __restrict__ bng, const float* __restrict__ bnb,
                        const float* __restrict__ psb, const float* __restrict__ ptb) {
    int t = blockIdx.x * blockDim.x + threadIdx.x;
    if (t < 3 * DIM) {
        double mean = g_tsum[t] / NSRC;
        double var = g_tsumsq[t] / NSRC - mean * mean;
        float a = bng[t] * rsqrtf((float)var + BN_EPS);
        g_ta[t] = a;
        g_tc[t] = bnb[t] - a * (float)mean;
    }
    if (t < DIM) g_combB[t] = psb[t] + ptb[t];
}

__global__ void k_coef2(const float* __restrict__ peg, const float* __restrict__ peb) {
    int t = threadIdx.x;
    double s = 0.0, q = 0.0;
#pragma unroll
    for (int b2 = 0; b2 < 32; b2++) {
        s += g_psumB[b2 * DIM + t];
        q += g_psumsqB[b2 * DIM + t];
    }
    double mean = s / NEDGE;
    double var = q / NEDGE - mean * mean;
    float a = peg[t] * rsqrtf((float)var + BN_EPS);
    g_peA[t] = a;
    g_peC[t] = peb[t] - a * (float)mean;
}

// ---------------- scores (y fp16, includes srcterm) --------------------------
__global__ void k_scores(const float* __restrict__ sw) {
    int w = (blockIdx.x * blockDim.x + threadIdx.x) >> 5;
    int lane = threadIdx.x & 31;
    int e0 = w * 64;
    int c0 = 2 * lane, c1 = 2 * lane + 64;
    float a0 = g_peA[c0], a1 = g_peA[c0 + 1], a2 = g_peA[c1], a3 = g_peA[c1 + 1];
    float d0 = g_peC[c0], d1 = g_peC[c0 + 1], d2 = g_peC[c1], d3 = g_peC[c1 + 1];
    float w0 = sw[c0], w1 = sw[c0 + 1], w2 = sw[c1], w3 = sw[c1 + 1];
    for (int e = e0; e < e0 + 64; e++) {
        const __half2* yr = (const __half2*)((const __half*)g_xg + (size_t)e * DIM);
        float2 f0 = __half22float2(yr[lane]);
        float2 f1 = __half22float2(yr[lane + 32]);
        float p = fmaxf(a0 * f0.x + d0, 0.f) * w0
                + fmaxf(a1 * f0.y + d1, 0.f) * w1
                + fmaxf(a2 * f1.x + d2, 0.f) * w2
                + fmaxf(a3 * f1.y + d3, 0.f) * w3;
#pragma unroll
        for (int o = 16; o; o >>= 1) p += __shfl_xor_sync(0xffffffffu, p, o);
        if (lane == 0) g_scores[e] = p;
    }
}

// ---------------- top-k ------------------------------------------------------
__device__ __forceinline__ bool kbetter(float s1, int i1, float s2, int i2) {
    return (s1 > s2) || (s1 == s2 && i1 < i2);
}
__device__ __forceinline__ void top_insert(float* bs, int* bi, float v, int e) {
    if (!kbetter(v, e, bs[TOPN - 1], bi[TOPN - 1])) return;
    int p = TOPN - 1;
    while (p > 0 && kbetter(v, e, bs[p - 1], bi[p - 1])) {
        bs[p] = bs[p - 1]; bi[p] = bi[p - 1]; p--;
    }
    bs[p] = v; bi[p] = e;
}

__global__ void k_top_a() {
    float bs[TOPN]; int bi[TOPN];
#pragma unroll
    for (int j = 0; j < TOPN; j++) { bs[j] = -1e30f; bi[j] = 0x7fffffff; }
    int t = blockIdx.x * 256 + threadIdx.x;
    for (int e = t; e < NEDGE; e += 128 * 256) {
        top_insert(bs, bi, g_scores[e], e);
    }
    __shared__ float ss[256 * TOPN];
    __shared__ int si[256 * TOPN];
#pragma unroll
    for (int j = 0; j < TOPN; j++) {
        ss[threadIdx.x * TOPN + j] = bs[j];
        si[threadIdx.x * TOPN + j] = bi[j];
    }
    __syncthreads();
    if (threadIdx.x == 0) {
        float cs[TOPN]; int ci[TOPN];
#pragma unroll
        for (int j = 0; j < TOPN; j++) { cs[j] = -1e30f; ci[j] = 0x7fffffff; }
        for (int k = 0; k < 256 * TOPN; k++) top_insert(cs, ci, ss[k], si[k]);
        for (int j = 0; j < TOPN; j++) {
            g_cs[blockIdx.x * TOPN + j] = cs[j];
            g_ci[blockIdx.x * TOPN + j] = ci[j];
        }
    }
}

__global__ void k_top_b(float* __restrict__ out) {
    if (threadIdx.x == 0) {
        float cs[TOPN]; int ci[TOPN];
#pragma unroll
        for (int j = 0; j < TOPN; j++) { cs[j] = -1e30f; ci[j] = 0x7fffffff; }
        for (int k = 0; k < 128 * TOPN; k++) top_insert(cs, ci, g_cs[k], g_ci[k]);
        for (int j = 0; j < TOPN; j++) {
            out[(size_t)NSRC * DIM + j] = cs[j];
            out[(size_t)NSRC * DIM + TOPN + j] = (float)ci[j];
        }
    }
}

// ---------------- host entry -------------------------------------------------
extern "C" void kernel_launch(void* const* d_in, const int* in_sizes, int n_in,
                              void* d_out, int out_size) {
    bool dictorder = (in_sizes[2] == NEDGE);
    const float* paths = (const float*)d_in[0];
    const float* pf    = (const float*)d_in[1];
    const int*   sid   = (const int*)d_in[dictorder ? 2 : 19];
    int b = dictorder ? 3 : 2;
    const float* cew = (const float*)d_in[b + 0];
    const float* ceb = (const float*)d_in[b + 1];
    const float* w1  = (const float*)d_in[b + 2];
    const float* bng = (const float*)d_in[b + 3];
    const float* bnb = (const float*)d_in[b + 4];
    const float* w2  = (const float*)d_in[b + 5];
    const float* l1W = (const float*)d_in[b + 6];
    const float* l1b = (const float*)d_in[b + 7];
    const float* l2W = (const float*)d_in[b + 8];
    const float* l2b = (const float*)d_in[b + 9];
    const float* psW = (const float*)d_in[b + 10];
    const float* psb = (const float*)d_in[b + 11];
    const float* ptW = (const float*)d_in[b + 12];
    const float* ptb = (const float*)d_in[b + 13];
    const float* peg = (const float*)d_in[b + 14];
    const float* peb = (const float*)d_in[b + 15];
    const float* sw  = (const float*)d_in[b + 16];
    float* out = (float*)d_out;

    void *p_agg, *p_Wc, *p_Wei1, *p_T, *p_cvec;
    void *p_Wbh, *p_Wbl, *p_Wch, *p_Wcl, *p_l2h, *p_l2l, *p_psh, *p_psl;
    cudaGetSymbolAddress(&p_agg, g_agg);
    cudaGetSymbolAddress(&p_Wc, g_Wc);
    cudaGetSymbolAddress(&p_Wei1, g_Wei1);
    cudaGetSymbolAddress(&p_T, g_T);
    cudaGetSymbolAddress(&p_cvec, g_cvec);
    cudaGetSymbolAddress(&p_Wbh, g_Wbh);
    cudaGetSymbolAddress(&p_Wbl, g_Wbl);
    cudaGetSymbolAddress(&p_Wch, g_Wch);
    cudaGetSymbolAddress(&p_Wcl, g_Wcl);
    cudaGetSymbolAddress(&p_l2h, g_l2h);
    cudaGetSymbolAddress(&p_l2l, g_l2l);
    cudaGetSymbolAddress(&p_psh, g_psh);
    cudaGetSymbolAddress(&p_psl, g_psl);
    const __nv_bfloat16* Wbh = (const __nv_bfloat16*)p_Wbh;
    const __nv_bfloat16* Wbl = (const __nv_bfloat16*)p_Wbl;
    const __nv_bfloat16* Wch = (const __nv_bfloat16*)p_Wch;
    const __nv_bfloat16* Wcl = (const __nv_bfloat16*)p_Wcl;
    const __nv_bfloat16* l2h = (const __nv_bfloat16*)p_l2h;
    const __nv_bfloat16* l2l = (const __nv_bfloat16*)p_l2l;
    const __nv_bfloat16* psh = (const __nv_bfloat16*)p_psh;
    const __nv_bfloat16* psl = (const __nv_bfloat16*)p_psl;

    cudaFuncSetAttribute(k_edge_gemm, cudaFuncAttributeMaxDynamicSharedMemorySize, EG_SMEM);
    cudaFuncSetAttribute(k_ncat, cudaFuncAttributeMaxDynamicSharedMemorySize, NC_SMEM);
    cudaFuncSetAttribute(k_nfused, cudaFuncAttributeMaxDynamicSharedMemorySize, NF_SMEM);

    const int NODE_BLKS = (NSRC + 127) / 128;   // 79

    // ---- fork: weight preps (input-only) overlap sort+agg ----
    cudaStream_t s2;
    cudaStreamCreateWithFlags(&s2, cudaStreamNonBlocking);
    cudaEvent_t evFork, evJoin;
    cudaEventCreateWithFlags(&evFork, cudaEventDisableTiming);
    cudaEventCreateWithFlags(&evJoin, cudaEventDisableTiming);

    cudaEventRecord(evFork, 0);
    cudaStreamWaitEvent(s2, evFork, 0);
    k_prepB<<<128, 256, 0, s2>>>(ptW);
    gemm128<<<dim3(1, 3), 256, 0, s2>>>(w2, DIM, DIM, DIM, (long)DIM * DIM,
                                        l1W, (long)DIM * DIM, (float*)p_Wc, (long)DIM * DIM);
    gemm128<<<dim3(2, 3), 256, 0, s2>>>(cew, EDIM, DIM, DIM, (long)EDIM * DIM,
                                        w1, (long)DIM * DIM, (float*)p_Wei1, (long)EDIM * DIM);
    k_cvec<<<3, 128, 0, s2>>>(ceb, w1);
    k_prepWbig<<<dim3(192, 3), 256, 0, s2>>>(w1);
    k_prepWgen<<<192, 256, 0, s2>>>((const float*)p_Wc, (__nv_bfloat16*)p_Wch,
                                    (__nv_bfloat16*)p_Wcl, 384, 384);
    k_prepWgen<<<64, 256, 0, s2>>>(l2W, (__nv_bfloat16*)p_l2h, (__nv_bfloat16*)p_l2l, 128, 128);
    k_prepWgen<<<64, 256, 0, s2>>>(psW, (__nv_bfloat16*)p_psh, (__nv_bfloat16*)p_psl, 128, 128);
    cudaEventRecord(evJoin, s2);

    // ---- main stream: sort + agg ----
    k_reset<<<40, 256>>>();
    k_hist<<<(NEDGE + 255) / 256, 256>>>(sid);
    k_scan<<<1, 1024>>>();
    k_scatter<<<(NEDGE + 255) / 256, 256>>>(sid);
    k_agg<<<(NSRC * 32 + 255) / 256, 256>>>(pf);

    // ---- join: preps + agg both ready ----
    cudaStreamWaitEvent(0, evJoin, 0);

    // T_cat = [agg|paths] @ Wbig_i + c_i  (+ BN stats)
    k_ncat<<<dim3(NODE_BLKS, 3), 256, NC_SMEM>>>(
        (const float*)p_agg, paths, Wbh, Wbl, (const float*)p_cvec, (float*)p_T);
    k_coef1<<<2, 256>>>(bng, bnb, psb, ptb);

    // fused: h2 -> node_emb(out) -> srcterm, one launch
    k_nfused<<<NODE_BLKS, 256, NF_SMEM>>>(l1b, l2b, Wch, Wcl, l2h, l2l, psh, psl, out);

    // edge GEMM (fp16 single-product) with fused srcterm add + BN stats
    k_edge_gemm<<<NEDGE / 128, 256, EG_SMEM>>>(pf, sid);

    k_coef2<<<1, 128>>>(peg, peb);
    k_scores<<<NEDGE / 512, 256>>>(sw);
    k_top_a<<<128, 256>>>();
    k_top_b<<<1, 32>>>(out);
    // stream/events intentionally not destroyed (capture-active; no device mem)
}